// round 8
// baseline (speedup 1.0000x reference)
#include <cuda_runtime.h>
#include <cstdint>
#include <cstddef>

#define B_  4
#define T_  1024
#define F_  256
#define D_  128
#define BT  (B_*T_)
#define NC  64
#define CH  16

// ---------------- scratch (static device globals: no allocation allowed) ----------------
__device__ float g_xn[(size_t)BT*F_];          // layernormed x
__device__ float g_P[(size_t)BT*512];          // [row][ K(128) | Q(128) | V(128) | SP(128) ]
__device__ float g_kvsum[(size_t)B_*NC*D_*D_]; // chunk KV sums -> in-place exclusive prefix
__device__ float g_zsum[(size_t)B_*NC*D_];     // chunk K sums  -> in-place exclusive prefix
__device__ float g_attn[(size_t)BT*D_];        // num/den

__device__ __forceinline__ float phi(float v) { return v > 0.f ? v + 1.f : expf(v); }

// ---------------- 1) LayerNorm ----------------
__global__ void ln_kernel(const float* __restrict__ x,
                          const float* __restrict__ gamma,
                          const float* __restrict__ beta) {
    int row = blockIdx.x;
    int tid = threadIdx.x;
    float v = x[(size_t)row*F_ + tid];
    float s = v, s2 = v*v;
    #pragma unroll
    for (int o = 16; o; o >>= 1) {
        s  += __shfl_xor_sync(0xffffffffu, s,  o);
        s2 += __shfl_xor_sync(0xffffffffu, s2, o);
    }
    __shared__ float ss[8], ss2[8];
    int wid = tid >> 5, lane = tid & 31;
    if (lane == 0) { ss[wid] = s; ss2[wid] = s2; }
    __syncthreads();
    float ts = 0.f, ts2 = 0.f;
    #pragma unroll
    for (int i = 0; i < 8; i++) { ts += ss[i]; ts2 += ss2[i]; }
    float mu  = ts * (1.f/F_);
    float var = ts2 * (1.f/F_) - mu*mu;
    float r   = rsqrtf(var + 1e-5f);
    g_xn[(size_t)row*F_ + tid] = (v - mu) * r * gamma[tid] + beta[tid];
}

// ---------------- 2) fused projection GEMM: P = xn @ [Wk;Wq;Wv;Ws]^T ----------------
// 128x128 block tile, BK=8, 8x8 microtile, 256 threads. grid = (32, 4); blockIdx.y picks matrix.
__global__ void __launch_bounds__(256) proj_gemm(const float* __restrict__ Wk,
                                                 const float* __restrict__ Wq,
                                                 const float* __restrict__ Wv,
                                                 const float* __restrict__ Ws) {
    const int bm = blockIdx.x, bn = blockIdx.y;
    const float* W = (bn == 0) ? Wk : (bn == 1) ? Wq : (bn == 2) ? Wv : Ws;
    __shared__ float As[8][128];
    __shared__ float Bs[8][128];
    int tid = threadIdx.x;
    int lrow = tid >> 1;              // 0..127
    int lk   = (tid & 1) * 4;         // 0 or 4
    int tx = tid & 15, ty = tid >> 4; // 16x16 thread grid

    float acc[8][8];
    #pragma unroll
    for (int i = 0; i < 8; i++)
        #pragma unroll
        for (int j = 0; j < 8; j++) acc[i][j] = 0.f;

    const float* Aptr = g_xn + (size_t)(bm*128 + lrow)*F_ + lk;
    const float* Wptr = W    + (size_t)lrow*F_ + lk;

    for (int k0 = 0; k0 < F_; k0 += 8) {
        float4 a = *(const float4*)(Aptr + k0);
        float4 w = *(const float4*)(Wptr + k0);
        As[lk+0][lrow] = a.x; As[lk+1][lrow] = a.y; As[lk+2][lrow] = a.z; As[lk+3][lrow] = a.w;
        Bs[lk+0][lrow] = w.x; Bs[lk+1][lrow] = w.y; Bs[lk+2][lrow] = w.z; Bs[lk+3][lrow] = w.w;
        __syncthreads();
        #pragma unroll
        for (int k = 0; k < 8; k++) {
            float4 a0 = *(const float4*)&As[k][ty*4];
            float4 a1 = *(const float4*)&As[k][ty*4 + 64];
            float4 b0 = *(const float4*)&Bs[k][tx*4];
            float4 b1 = *(const float4*)&Bs[k][tx*4 + 64];
            float am[8] = {a0.x,a0.y,a0.z,a0.w, a1.x,a1.y,a1.z,a1.w};
            float bw[8] = {b0.x,b0.y,b0.z,b0.w, b1.x,b1.y,b1.z,b1.w};
            #pragma unroll
            for (int i = 0; i < 8; i++)
                #pragma unroll
                for (int j = 0; j < 8; j++) acc[i][j] += am[i]*bw[j];
        }
        __syncthreads();
    }

    const bool doPhi = (bn < 2); // K and Q get elu+1
    #pragma unroll
    for (int i = 0; i < 8; i++) {
        int m = bm*128 + ((i < 4) ? (ty*4 + i) : (64 + ty*4 + i - 4));
        float v[8];
        #pragma unroll
        for (int j = 0; j < 8; j++) v[j] = doPhi ? phi(acc[i][j]) : acc[i][j];
        float* outp = g_P + (size_t)m*512 + bn*128;
        *(float4*)(outp + tx*4)      = make_float4(v[0], v[1], v[2], v[3]);
        *(float4*)(outp + 64 + tx*4) = make_float4(v[4], v[5], v[6], v[7]);
    }
}

// ---------------- 3) per-chunk KV sums + K sums ----------------
__global__ void __launch_bounds__(256) chunksum_kernel() {
    int blk = blockIdx.x;
    int b = blk >> 6, c = blk & 63;
    __shared__ float Kc[CH][D_], Vc[CH][D_];
    int tid = threadIdx.x, wid = tid >> 5, lane = tid & 31;
    int rowbase = b*T_ + c*CH;

    for (int i = tid; i < CH*32; i += 256) {
        int t = i >> 5, c4 = (i & 31) * 4;
        const float* p = g_P + (size_t)(rowbase + t)*512;
        *(float4*)&Kc[t][c4] = *(const float4*)(p + c4);
        *(float4*)&Vc[t][c4] = *(const float4*)(p + 256 + c4);
    }
    __syncthreads();

    float4 acc[16];
    #pragma unroll
    for (int r = 0; r < 16; r++) acc[r] = make_float4(0.f,0.f,0.f,0.f);

    #pragma unroll
    for (int t = 0; t < CH; t++) {
        float4 v = *(const float4*)&Vc[t][lane*4];
        #pragma unroll
        for (int r = 0; r < 16; r++) {
            float k = Kc[t][wid + 8*r];
            acc[r].x += k*v.x; acc[r].y += k*v.y; acc[r].z += k*v.z; acc[r].w += k*v.w;
        }
    }
    size_t obase = ((size_t)(b*NC + c)*D_ + wid)*D_ + lane*4;
    #pragma unroll
    for (int r = 0; r < 16; r++)
        *(float4*)&g_kvsum[obase + (size_t)r*8*D_] = acc[r];

    if (tid < 128) {
        float s = 0.f;
        #pragma unroll
        for (int t = 0; t < CH; t++) s += Kc[t][tid];
        g_zsum[(size_t)(b*NC + c)*D_ + tid] = s;
    }
}

// ---------------- 4) exclusive prefix over chunks (in place), seeded by S0/Z0 ----------------
// Front-batched register scan: 32 independent loads in flight (MLP~32), prefix
// in registers, 32 stores — two halves of the 64-chunk series per thread.
__global__ void __launch_bounds__(256) prefix_s_kernel(const float* __restrict__ S0) {
    int gid = blockIdx.x*256 + threadIdx.x;  // B*D*D = 65536
    int b = gid >> 14, ij = gid & 16383;
    size_t base = (size_t)b*NC*16384 + ij;
    float acc = S0[(size_t)b*16384 + ij];

    float v[32];
    // ---- chunks 0..31 ----
    #pragma unroll
    for (int c = 0; c < 32; c++) v[c] = g_kvsum[base + (size_t)c*16384];
    #pragma unroll
    for (int c = 0; c < 32; c++) { float t = v[c]; v[c] = acc; acc += t; }
    #pragma unroll
    for (int c = 0; c < 32; c++) g_kvsum[base + (size_t)c*16384] = v[c];
    // ---- chunks 32..63 ----
    #pragma unroll
    for (int c = 0; c < 32; c++) v[c] = g_kvsum[base + (size_t)(c+32)*16384];
    #pragma unroll
    for (int c = 0; c < 32; c++) { float t = v[c]; v[c] = acc; acc += t; }
    #pragma unroll
    for (int c = 0; c < 32; c++) g_kvsum[base + (size_t)(c+32)*16384] = v[c];
}

__global__ void prefix_z_kernel(const float* __restrict__ Z0) {
    int gid = blockIdx.x*256 + threadIdx.x;  // B*D = 512
    int b = gid >> 7, i = gid & 127;
    float acc = Z0[b*128 + i];
    float v[NC];
    #pragma unroll
    for (int c = 0; c < NC; c++) v[c] = g_zsum[(size_t)(b*NC + c)*D_ + i];
    #pragma unroll
    for (int c = 0; c < NC; c++) { float t = v[c]; v[c] = acc; acc += t; }
    #pragma unroll
    for (int c = 0; c < NC; c++) g_zsum[(size_t)(b*NC + c)*D_ + i] = v[c];
}

// ---------------- 5) main scan: S, Z, num, den, attn fused ----------------
__global__ void __launch_bounds__(256) scan_kernel(float* __restrict__ Sout,
                                                   float* __restrict__ Zout) {
    int blk = blockIdx.x;
    int b = blk >> 6, c = blk & 63;
    int tid = threadIdx.x, wid = tid >> 5, lane = tid & 31;

    __shared__ float Kc[CH][D_], Qc[CH][D_], Vc[CH][D_];
    __shared__ float partial[8][D_];
    __shared__ float sden[4];

    int rowbase = b*T_ + c*CH;
    for (int i = tid; i < CH*32; i += 256) {
        int t = i >> 5, c4 = (i & 31) * 4;
        const float* p = g_P + (size_t)(rowbase + t)*512;
        *(float4*)&Kc[t][c4] = *(const float4*)(p + c4);
        *(float4*)&Qc[t][c4] = *(const float4*)(p + 128 + c4);
        *(float4*)&Vc[t][c4] = *(const float4*)(p + 256 + c4);
    }

    // load state prefix into registers: thread owns rows {wid+8r}, cols [4*lane, 4*lane+4)
    float4 st[16];
    size_t pbase = ((size_t)(b*NC + c)*D_ + wid)*D_ + lane*4;
    #pragma unroll
    for (int r = 0; r < 16; r++)
        st[r] = *(const float4*)&g_kvsum[pbase + (size_t)r*8*D_];

    float zr = (tid < 128) ? g_zsum[(size_t)(b*NC + c)*D_ + tid] : 0.f;
    __syncthreads();

    for (int t = 0; t < CH; t++) {
        int rowt = rowbase + t;
        float4 v = *(const float4*)&Vc[t][lane*4];
        float4 pn = make_float4(0.f,0.f,0.f,0.f);
        float* sbase = Sout + ((size_t)rowt*D_ + wid)*D_ + lane*4;
        #pragma unroll
        for (int r = 0; r < 16; r++) {
            float k = Kc[t][wid + 8*r];
            st[r].x += k*v.x; st[r].y += k*v.y; st[r].z += k*v.z; st[r].w += k*v.w;
            *(float4*)(sbase + (size_t)r*8*D_) = st[r];
            float q = Qc[t][wid + 8*r];
            pn.x += q*st[r].x; pn.y += q*st[r].y; pn.z += q*st[r].z; pn.w += q*st[r].w;
        }
        *(float4*)&partial[wid][lane*4] = pn;
        __syncthreads();

        float numj = 0.f;
        if (tid < 128) {
            #pragma unroll
            for (int w = 0; w < 8; w++) numj += partial[w][tid];
            zr += Kc[t][tid];
            Zout[(size_t)rowt*D_ + tid] = zr;
            float dp = Qc[t][tid] * zr;
            #pragma unroll
            for (int o = 16; o; o >>= 1) dp += __shfl_xor_sync(0xffffffffu, dp, o);
            if (lane == 0) sden[wid] = dp;
        }
        __syncthreads();

        if (tid < 128) {
            float den = sden[0] + sden[1] + sden[2] + sden[3] + 1e-5f;
            g_attn[(size_t)rowt*D_ + tid] = numj / den;
        }
    }
}

// ---------------- 6) MLP tail: relu(relu(attn@W1^T+b1)@W2^T+b2) + sp + bs ----------------
// 16 rows per block, W staged in smem [e][132] (padded), 256 threads.
#define WPAD 132
#define MLP_SMEM ((128*WPAD + 16*128 + 16*128) * 4)

__global__ void __launch_bounds__(256) mlp_kernel(const float* __restrict__ W1,
                                                  const float* __restrict__ b1,
                                                  const float* __restrict__ W2,
                                                  const float* __restrict__ b2,
                                                  const float* __restrict__ bs,
                                                  float* __restrict__ out) {
    extern __shared__ float sm[];
    float* sW = sm;                  // [e][WPAD]
    float* sA = sm + 128*WPAD;       // [16][128]
    float* sH = sA + 16*128;         // [16][128]

    int tid = threadIdx.x;
    int r0  = blockIdx.x * 16;
    int e   = tid & 127;
    int rr  = (tid >> 7) * 8;        // 0 or 8

    // load attn rows
    for (int i = tid; i < 16*32; i += 256) {
        int r = i >> 5, c4 = (i & 31) * 4;
        *(float4*)&sA[r*128 + c4] = *(const float4*)(g_attn + (size_t)(r0 + r)*128 + c4);
    }
    // load W1 -> sW[e][d]
    #pragma unroll
    for (int rep = 0; rep < 16; rep++) {
        int i = rep*256 + tid;
        int ee = i >> 5, d4 = (i & 31) * 4;
        *(float4*)&sW[ee*WPAD + d4] = *(const float4*)(W1 + (size_t)ee*128 + d4);
    }
    __syncthreads();

    float acc[8];
    #pragma unroll
    for (int i = 0; i < 8; i++) acc[i] = 0.f;
    for (int d4 = 0; d4 < 128; d4 += 4) {
        float4 w = *(const float4*)&sW[e*WPAD + d4];
        #pragma unroll
        for (int i = 0; i < 8; i++) {
            float4 a = *(const float4*)&sA[(rr + i)*128 + d4];
            acc[i] += a.x*w.x + a.y*w.y + a.z*w.z + a.w*w.w;
        }
    }
    float bb1 = __ldg(&b1[e]);
    #pragma unroll
    for (int i = 0; i < 8; i++)
        sH[(rr + i)*128 + e] = fmaxf(acc[i] + bb1, 0.f);
    __syncthreads();

    // load W2 -> sW
    #pragma unroll
    for (int rep = 0; rep < 16; rep++) {
        int i = rep*256 + tid;
        int ee = i >> 5, d4 = (i & 31) * 4;
        *(float4*)&sW[ee*WPAD + d4] = *(const float4*)(W2 + (size_t)ee*128 + d4);
    }
    __syncthreads();

    #pragma unroll
    for (int i = 0; i < 8; i++) acc[i] = 0.f;
    for (int d4 = 0; d4 < 128; d4 += 4) {
        float4 w = *(const float4*)&sW[e*WPAD + d4];
        #pragma unroll
        for (int i = 0; i < 8; i++) {
            float4 a = *(const float4*)&sH[(rr + i)*128 + d4];
            acc[i] += a.x*w.x + a.y*w.y + a.z*w.z + a.w*w.w;
        }
    }
    float bb2 = __ldg(&b2[e]);
    float bse = __ldg(&bs[e]);
    #pragma unroll
    for (int i = 0; i < 8; i++) {
        size_t row = (size_t)(r0 + rr + i);
        float sp = g_P[row*512 + 384 + e];
        out[row*128 + e] = fmaxf(acc[i] + bb2, 0.f) + sp + bse;
    }
}

// ---------------- launcher ----------------
extern "C" void kernel_launch(void* const* d_in, const int* in_sizes, int n_in,
                              void* d_out, int out_size) {
    const float* x    = (const float*)d_in[0];
    const float* S0   = (const float*)d_in[1];
    const float* Z0   = (const float*)d_in[2];
    const float* ln_g = (const float*)d_in[3];
    const float* ln_b = (const float*)d_in[4];
    const float* Wk   = (const float*)d_in[5];
    const float* Wq   = (const float*)d_in[6];
    const float* Wv   = (const float*)d_in[7];
    const float* W1   = (const float*)d_in[8];
    const float* b1   = (const float*)d_in[9];
    const float* W2   = (const float*)d_in[10];
    const float* b2   = (const float*)d_in[11];
    const float* Ws   = (const float*)d_in[12];
    const float* bs   = (const float*)d_in[13];

    float* out  = (float*)d_out;                       // [B,T,D]
    float* Sout = out  + (size_t)BT*D_;                // [B,T,D,D]
    float* Zout = Sout + (size_t)BT*D_*D_;             // [B,T,D]

    ln_kernel<<<BT, 256>>>(x, ln_g, ln_b);
    proj_gemm<<<dim3(BT/128, 4), 256>>>(Wk, Wq, Wv, Ws);
    chunksum_kernel<<<B_*NC, 256>>>();
    prefix_s_kernel<<<(B_*D_*D_)/256, 256>>>(S0);
    prefix_z_kernel<<<2, 256>>>(Z0);
    scan_kernel<<<B_*NC, 256>>>(Sout, Zout);
    cudaFuncSetAttribute(mlp_kernel, cudaFuncAttributeMaxDynamicSharedMemorySize, MLP_SMEM);
    mlp_kernel<<<BT/16, 256, MLP_SMEM>>>(W1, b1, W2, b2, bs, out);
}

// round 12
// speedup vs baseline: 1.2333x; 1.2333x over previous
#include <cuda_runtime.h>
#include <cuda_bf16.h>
#include <cstdint>
#include <cstddef>

#define B_  4
#define T_  1024
#define F_  256
#define D_  128
#define BT  (B_*T_)
#define NC  64
#define CH  16

// single dynamic smem symbol shared by all kernels (cast per-kernel)
extern __shared__ unsigned char sm_raw[];

// ---------------- scratch (static device globals: no allocation allowed) ----------------
__device__ __align__(16) __nv_bfloat16 g_xhi[(size_t)BT*F_];   // LN output, bf16 high part
__device__ __align__(16) __nv_bfloat16 g_xlo[(size_t)BT*F_];   // LN output, bf16 low part
__device__ __align__(16) __nv_bfloat16 g_whi[(size_t)4*D_*F_]; // [bn][128][256] weights hi
__device__ __align__(16) __nv_bfloat16 g_wlo[(size_t)4*D_*F_]; // weights lo
__device__ float g_P[(size_t)BT*512];            // [row][ K(128) | Q(128) | V(128) | SP(128) ]
__device__ float g_kvsum[(size_t)B_*NC*D_*D_];   // chunk KV sums -> in-place exclusive prefix
__device__ float g_zsum[(size_t)B_*NC*D_];       // chunk K sums  -> in-place exclusive prefix
__device__ float g_attn[(size_t)BT*D_];          // num/den

__device__ __forceinline__ float phi(float v) { return v > 0.f ? v + 1.f : expf(v); }

// ---------------- 0) weight split fp32 -> bf16 hi/lo ----------------
__global__ void conv_w_kernel(const float* __restrict__ Wk, const float* __restrict__ Wq,
                              const float* __restrict__ Wv, const float* __restrict__ Ws) {
    int idx = blockIdx.x*256 + threadIdx.x;      // 0..32767
    const float* srcs[4] = {Wk, Wq, Wv, Ws};
    #pragma unroll
    for (int bn = 0; bn < 4; bn++) {
        float v = srcs[bn][idx];
        __nv_bfloat16 h = __float2bfloat16(v);
        __nv_bfloat16 l = __float2bfloat16(v - __bfloat162float(h));
        g_whi[(size_t)bn*32768 + idx] = h;
        g_wlo[(size_t)bn*32768 + idx] = l;
    }
}

// ---------------- 1) LayerNorm -> bf16 hi/lo ----------------
__global__ void ln_kernel(const float* __restrict__ x,
                          const float* __restrict__ gamma,
                          const float* __restrict__ beta) {
    int row = blockIdx.x;
    int tid = threadIdx.x;
    float v = x[(size_t)row*F_ + tid];
    float s = v, s2 = v*v;
    #pragma unroll
    for (int o = 16; o; o >>= 1) {
        s  += __shfl_xor_sync(0xffffffffu, s,  o);
        s2 += __shfl_xor_sync(0xffffffffu, s2, o);
    }
    __shared__ float ss[8], ss2[8];
    int wid = tid >> 5, lane = tid & 31;
    if (lane == 0) { ss[wid] = s; ss2[wid] = s2; }
    __syncthreads();
    float ts = 0.f, ts2 = 0.f;
    #pragma unroll
    for (int i = 0; i < 8; i++) { ts += ss[i]; ts2 += ss2[i]; }
    float mu  = ts * (1.f/F_);
    float var = ts2 * (1.f/F_) - mu*mu;
    float r   = rsqrtf(var + 1e-5f);
    float xn  = (v - mu) * r * gamma[tid] + beta[tid];
    __nv_bfloat16 h = __float2bfloat16(xn);
    __nv_bfloat16 l = __float2bfloat16(xn - __bfloat162float(h));
    g_xhi[(size_t)row*F_ + tid] = h;
    g_xlo[(size_t)row*F_ + tid] = l;
}

// ---------------- 2) projection GEMM via split-bf16 HMMA ----------------
// C[128x128] per block; grid (32, 4); 8 warps in 2(m) x 4(n) grid, warp tile 64x32.
// K staged 64-wide in dynamic smem; row stride 72 bf16 (36 words) => conflict-free frag loads.
#define KSTG 64
#define ASTR 72
#define PJ_SMEM (4*128*ASTR*2)   // Ah, Al, Wh, Wl (bytes)

__device__ __forceinline__ void mma_bf16(float& c0, float& c1, float& c2, float& c3,
                                         uint32_t a0, uint32_t a1, uint32_t a2, uint32_t a3,
                                         uint32_t b0, uint32_t b1) {
    asm volatile("mma.sync.aligned.m16n8k16.row.col.f32.bf16.bf16.f32 "
                 "{%0,%1,%2,%3}, {%4,%5,%6,%7}, {%8,%9}, {%0,%1,%2,%3};"
                 : "+f"(c0), "+f"(c1), "+f"(c2), "+f"(c3)
                 : "r"(a0), "r"(a1), "r"(a2), "r"(a3), "r"(b0), "r"(b1));
}

__global__ void __launch_bounds__(256) proj_gemm_bf16() {
    __nv_bfloat16* Ah = (__nv_bfloat16*)sm_raw;
    __nv_bfloat16* Al = Ah + 128*ASTR;
    __nv_bfloat16* Wh = Al + 128*ASTR;
    __nv_bfloat16* Wl = Wh + 128*ASTR;

    const int bm = blockIdx.x, bn = blockIdx.y;
    const int tid = threadIdx.x;
    const int wid = tid >> 5, lane = tid & 31;
    const int warp_m = wid >> 2, warp_n = wid & 3;
    const int g  = lane >> 2;          // 0..7
    const int c2 = (lane & 3) * 2;     // 0,2,4,6

    // loader mapping: 2 threads per row, 32 bf16 each (4 x uint4 = 4 x 8 elements)
    const int lrow = tid >> 1;
    const int lcol = (tid & 1) * 32;

    float c[4][4][4];
    #pragma unroll
    for (int mt = 0; mt < 4; mt++)
        #pragma unroll
        for (int nt = 0; nt < 4; nt++)
            #pragma unroll
            for (int i = 0; i < 4; i++) c[mt][nt][i] = 0.f;

    const size_t arow = (size_t)(bm*128 + lrow)*F_;
    const size_t wrow = (size_t)bn*32768 + (size_t)lrow*F_;

    for (int k0 = 0; k0 < F_; k0 += KSTG) {
        // stage: each thread copies 32 bf16 per array (uint4 = 8 bf16 -> 4 stores)
        #pragma unroll
        for (int j = 0; j < 4; j++) {
            int co = lcol + j*8;
            *(uint4*)&Ah[lrow*ASTR + co] = *(const uint4*)&g_xhi[arow + k0 + co];
            *(uint4*)&Al[lrow*ASTR + co] = *(const uint4*)&g_xlo[arow + k0 + co];
            *(uint4*)&Wh[lrow*ASTR + co] = *(const uint4*)&g_whi[wrow + k0 + co];
            *(uint4*)&Wl[lrow*ASTR + co] = *(const uint4*)&g_wlo[wrow + k0 + co];
        }
        __syncthreads();

        #pragma unroll
        for (int ks = 0; ks < KSTG/16; ks++) {
            const int kb = ks*16;
            uint32_t ah[4][4], al[4][4], bh[4][2], bl[4][2];
            #pragma unroll
            for (int mt = 0; mt < 4; mt++) {
                int r0 = warp_m*64 + mt*16 + g;
                ah[mt][0] = *(const uint32_t*)&Ah[ r0     *ASTR + kb + c2];
                ah[mt][1] = *(const uint32_t*)&Ah[(r0+8)  *ASTR + kb + c2];
                ah[mt][2] = *(const uint32_t*)&Ah[ r0     *ASTR + kb + 8 + c2];
                ah[mt][3] = *(const uint32_t*)&Ah[(r0+8)  *ASTR + kb + 8 + c2];
                al[mt][0] = *(const uint32_t*)&Al[ r0     *ASTR + kb + c2];
                al[mt][1] = *(const uint32_t*)&Al[(r0+8)  *ASTR + kb + c2];
                al[mt][2] = *(const uint32_t*)&Al[ r0     *ASTR + kb + 8 + c2];
                al[mt][3] = *(const uint32_t*)&Al[(r0+8)  *ASTR + kb + 8 + c2];
            }
            #pragma unroll
            for (int nt = 0; nt < 4; nt++) {
                int n = warp_n*32 + nt*8 + g;
                bh[nt][0] = *(const uint32_t*)&Wh[n*ASTR + kb + c2];
                bh[nt][1] = *(const uint32_t*)&Wh[n*ASTR + kb + 8 + c2];
                bl[nt][0] = *(const uint32_t*)&Wl[n*ASTR + kb + c2];
                bl[nt][1] = *(const uint32_t*)&Wl[n*ASTR + kb + 8 + c2];
            }
            #pragma unroll
            for (int mt = 0; mt < 4; mt++)
                #pragma unroll
                for (int nt = 0; nt < 4; nt++) {
                    float* cc = c[mt][nt];
                    mma_bf16(cc[0],cc[1],cc[2],cc[3], ah[mt][0],ah[mt][1],ah[mt][2],ah[mt][3], bh[nt][0],bh[nt][1]);
                    mma_bf16(cc[0],cc[1],cc[2],cc[3], ah[mt][0],ah[mt][1],ah[mt][2],ah[mt][3], bl[nt][0],bl[nt][1]);
                    mma_bf16(cc[0],cc[1],cc[2],cc[3], al[mt][0],al[mt][1],al[mt][2],al[mt][3], bh[nt][0],bh[nt][1]);
                }
        }
        __syncthreads();
    }

    const bool doPhi = (bn < 2);
    #pragma unroll
    for (int mt = 0; mt < 4; mt++) {
        #pragma unroll
        for (int nt = 0; nt < 4; nt++) {
            int row = bm*128 + warp_m*64 + mt*16 + g;
            int col = warp_n*32 + nt*8 + c2;
            float v0 = c[mt][nt][0], v1 = c[mt][nt][1];
            float v2 = c[mt][nt][2], v3 = c[mt][nt][3];
            if (doPhi) { v0 = phi(v0); v1 = phi(v1); v2 = phi(v2); v3 = phi(v3); }
            float* p0 = g_P + (size_t)row*512 + bn*128 + col;
            float* p1 = g_P + (size_t)(row+8)*512 + bn*128 + col;
            *(float2*)p0 = make_float2(v0, v1);
            *(float2*)p1 = make_float2(v2, v3);
        }
    }
}

// ---------------- 3) per-chunk KV sums + K sums ----------------
__global__ void __launch_bounds__(256) chunksum_kernel() {
    int blk = blockIdx.x;
    int b = blk >> 6, c = blk & 63;
    __shared__ float Kc[CH][D_], Vc[CH][D_];
    int tid = threadIdx.x, wid = tid >> 5, lane = tid & 31;
    int rowbase = b*T_ + c*CH;

    for (int i = tid; i < CH*32; i += 256) {
        int t = i >> 5, c4 = (i & 31) * 4;
        const float* p = g_P + (size_t)(rowbase + t)*512;
        *(float4*)&Kc[t][c4] = *(const float4*)(p + c4);
        *(float4*)&Vc[t][c4] = *(const float4*)(p + 256 + c4);
    }
    __syncthreads();

    float4 acc[16];
    #pragma unroll
    for (int r = 0; r < 16; r++) acc[r] = make_float4(0.f,0.f,0.f,0.f);

    #pragma unroll
    for (int t = 0; t < CH; t++) {
        float4 v = *(const float4*)&Vc[t][lane*4];
        #pragma unroll
        for (int r = 0; r < 16; r++) {
            float k = Kc[t][wid + 8*r];
            acc[r].x += k*v.x; acc[r].y += k*v.y; acc[r].z += k*v.z; acc[r].w += k*v.w;
        }
    }
    size_t obase = ((size_t)(b*NC + c)*D_ + wid)*D_ + lane*4;
    #pragma unroll
    for (int r = 0; r < 16; r++)
        *(float4*)&g_kvsum[obase + (size_t)r*8*D_] = acc[r];

    if (tid < 128) {
        float s = 0.f;
        #pragma unroll
        for (int t = 0; t < CH; t++) s += Kc[t][tid];
        g_zsum[(size_t)(b*NC + c)*D_ + tid] = s;
    }
}

// ---------------- 4) exclusive prefix over chunks (in place), seeded by S0/Z0 ----------------
__global__ void __launch_bounds__(256) prefix_s_kernel(const float* __restrict__ S0) {
    int gid = blockIdx.x*256 + threadIdx.x;  // B*D*D = 65536
    int b = gid >> 14, ij = gid & 16383;
    size_t base = (size_t)b*NC*16384 + ij;
    float acc = S0[(size_t)b*16384 + ij];

    float v[32];
    #pragma unroll
    for (int c = 0; c < 32; c++) v[c] = g_kvsum[base + (size_t)c*16384];
    #pragma unroll
    for (int c = 0; c < 32; c++) { float t = v[c]; v[c] = acc; acc += t; }
    #pragma unroll
    for (int c = 0; c < 32; c++) g_kvsum[base + (size_t)c*16384] = v[c];
    #pragma unroll
    for (int c = 0; c < 32; c++) v[c] = g_kvsum[base + (size_t)(c+32)*16384];
    #pragma unroll
    for (int c = 0; c < 32; c++) { float t = v[c]; v[c] = acc; acc += t; }
    #pragma unroll
    for (int c = 0; c < 32; c++) g_kvsum[base + (size_t)(c+32)*16384] = v[c];
}

__global__ void prefix_z_kernel(const float* __restrict__ Z0) {
    int gid = blockIdx.x*256 + threadIdx.x;  // B*D = 512
    int b = gid >> 7, i = gid & 127;
    float acc = Z0[b*128 + i];
    float v[NC];
    #pragma unroll
    for (int c = 0; c < NC; c++) v[c] = g_zsum[(size_t)(b*NC + c)*D_ + i];
    #pragma unroll
    for (int c = 0; c < NC; c++) { float t = v[c]; v[c] = acc; acc += t; }
    #pragma unroll
    for (int c = 0; c < NC; c++) g_zsum[(size_t)(b*NC + c)*D_ + i] = v[c];
}

// ---------------- 5) main scan: S, Z, num, den, attn fused ----------------
__global__ void __launch_bounds__(256) scan_kernel(float* __restrict__ Sout,
                                                   float* __restrict__ Zout) {
    int blk = blockIdx.x;
    int b = blk >> 6, c = blk & 63;
    int tid = threadIdx.x, wid = tid >> 5, lane = tid & 31;

    __shared__ float Kc[CH][D_], Qc[CH][D_], Vc[CH][D_];
    __shared__ float partial[8][D_];
    __shared__ float sden[4];

    int rowbase = b*T_ + c*CH;
    for (int i = tid; i < CH*32; i += 256) {
        int t = i >> 5, c4 = (i & 31) * 4;
        const float* p = g_P + (size_t)(rowbase + t)*512;
        *(float4*)&Kc[t][c4] = *(const float4*)(p + c4);
        *(float4*)&Qc[t][c4] = *(const float4*)(p + 128 + c4);
        *(float4*)&Vc[t][c4] = *(const float4*)(p + 256 + c4);
    }

    float4 st[16];
    size_t pbase = ((size_t)(b*NC + c)*D_ + wid)*D_ + lane*4;
    #pragma unroll
    for (int r = 0; r < 16; r++)
        st[r] = *(const float4*)&g_kvsum[pbase + (size_t)r*8*D_];

    float zr = (tid < 128) ? g_zsum[(size_t)(b*NC + c)*D_ + tid] : 0.f;
    __syncthreads();

    for (int t = 0; t < CH; t++) {
        int rowt = rowbase + t;
        float4 v = *(const float4*)&Vc[t][lane*4];
        float4 pn = make_float4(0.f,0.f,0.f,0.f);
        float* sbase = Sout + ((size_t)rowt*D_ + wid)*D_ + lane*4;
        #pragma unroll
        for (int r = 0; r < 16; r++) {
            float k = Kc[t][wid + 8*r];
            st[r].x += k*v.x; st[r].y += k*v.y; st[r].z += k*v.z; st[r].w += k*v.w;
            *(float4*)(sbase + (size_t)r*8*D_) = st[r];
            float q = Qc[t][wid + 8*r];
            pn.x += q*st[r].x; pn.y += q*st[r].y; pn.z += q*st[r].z; pn.w += q*st[r].w;
        }
        *(float4*)&partial[wid][lane*4] = pn;
        __syncthreads();

        float numj = 0.f;
        if (tid < 128) {
            #pragma unroll
            for (int w = 0; w < 8; w++) numj += partial[w][tid];
            zr += Kc[t][tid];
            Zout[(size_t)rowt*D_ + tid] = zr;
            float dp = Qc[t][tid] * zr;
            #pragma unroll
            for (int o = 16; o; o >>= 1) dp += __shfl_xor_sync(0xffffffffu, dp, o);
            if (lane == 0) sden[wid] = dp;
        }
        __syncthreads();

        if (tid < 128) {
            float den = sden[0] + sden[1] + sden[2] + sden[3] + 1e-5f;
            g_attn[(size_t)rowt*D_ + tid] = numj / den;
        }
    }
}

// ---------------- 6) MLP tail ----------------
#define WPAD 132
#define MLP_SMEM ((128*WPAD + 16*128 + 16*128) * 4)

__global__ void __launch_bounds__(256) mlp_kernel(const float* __restrict__ W1,
                                                  const float* __restrict__ b1,
                                                  const float* __restrict__ W2,
                                                  const float* __restrict__ b2,
                                                  const float* __restrict__ bs,
                                                  float* __restrict__ out) {
    float* sW = (float*)sm_raw;
    float* sA = sW + 128*WPAD;
    float* sH = sA + 16*128;

    int tid = threadIdx.x;
    int r0  = blockIdx.x * 16;
    int e   = tid & 127;
    int rr  = (tid >> 7) * 8;

    for (int i = tid; i < 16*32; i += 256) {
        int r = i >> 5, c4 = (i & 31) * 4;
        *(float4*)&sA[r*128 + c4] = *(const float4*)(g_attn + (size_t)(r0 + r)*128 + c4);
    }
    #pragma unroll
    for (int rep = 0; rep < 16; rep++) {
        int i = rep*256 + tid;
        int ee = i >> 5, d4 = (i & 31) * 4;
        *(float4*)&sW[ee*WPAD + d4] = *(const float4*)(W1 + (size_t)ee*128 + d4);
    }
    __syncthreads();

    float acc[8];
    #pragma unroll
    for (int i = 0; i < 8; i++) acc[i] = 0.f;
    for (int d4 = 0; d4 < 128; d4 += 4) {
        float4 w = *(const float4*)&sW[e*WPAD + d4];
        #pragma unroll
        for (int i = 0; i < 8; i++) {
            float4 a = *(const float4*)&sA[(rr + i)*128 + d4];
            acc[i] += a.x*w.x + a.y*w.y + a.z*w.z + a.w*w.w;
        }
    }
    float bb1 = __ldg(&b1[e]);
    #pragma unroll
    for (int i = 0; i < 8; i++)
        sH[(rr + i)*128 + e] = fmaxf(acc[i] + bb1, 0.f);
    __syncthreads();

    #pragma unroll
    for (int rep = 0; rep < 16; rep++) {
        int i = rep*256 + tid;
        int ee = i >> 5, d4 = (i & 31) * 4;
        *(float4*)&sW[ee*WPAD + d4] = *(const float4*)(W2 + (size_t)ee*128 + d4);
    }
    __syncthreads();

    #pragma unroll
    for (int i = 0; i < 8; i++) acc[i] = 0.f;
    for (int d4 = 0; d4 < 128; d4 += 4) {
        float4 w = *(const float4*)&sW[e*WPAD + d4];
        #pragma unroll
        for (int i = 0; i < 8; i++) {
            float4 a = *(const float4*)&sH[(rr + i)*128 + d4];
            acc[i] += a.x*w.x + a.y*w.y + a.z*w.z + a.w*w.w;
        }
    }
    float bb2 = __ldg(&b2[e]);
    float bse = __ldg(&bs[e]);
    #pragma unroll
    for (int i = 0; i < 8; i++) {
        size_t row = (size_t)(r0 + rr + i);
        float sp = g_P[row*512 + 384 + e];
        out[row*128 + e] = fmaxf(acc[i] + bb2, 0.f) + sp + bse;
    }
}

// ---------------- launcher ----------------
extern "C" void kernel_launch(void* const* d_in, const int* in_sizes, int n_in,
                              void* d_out, int out_size) {
    const float* x    = (const float*)d_in[0];
    const float* S0   = (const float*)d_in[1];
    const float* Z0   = (const float*)d_in[2];
    const float* ln_g = (const float*)d_in[3];
    const float* ln_b = (const float*)d_in[4];
    const float* Wk   = (const float*)d_in[5];
    const float* Wq   = (const float*)d_in[6];
    const float* Wv   = (const float*)d_in[7];
    const float* W1   = (const float*)d_in[8];
    const float* b1   = (const float*)d_in[9];
    const float* W2   = (const float*)d_in[10];
    const float* b2   = (const float*)d_in[11];
    const float* Ws   = (const float*)d_in[12];
    const float* bs   = (const float*)d_in[13];

    float* out  = (float*)d_out;
    float* Sout = out  + (size_t)BT*D_;
    float* Zout = Sout + (size_t)BT*D_*D_;

    conv_w_kernel<<<128, 256>>>(Wk, Wq, Wv, Ws);
    ln_kernel<<<BT, 256>>>(x, ln_g, ln_b);
    cudaFuncSetAttribute(proj_gemm_bf16, cudaFuncAttributeMaxDynamicSharedMemorySize, PJ_SMEM);
    proj_gemm_bf16<<<dim3(BT/128, 4), 256, PJ_SMEM>>>();
    chunksum_kernel<<<B_*NC, 256>>>();
    prefix_s_kernel<<<(B_*D_*D_)/256, 256>>>(S0);
    prefix_z_kernel<<<2, 256>>>(Z0);
    scan_kernel<<<B_*NC, 256>>>(Sout, Zout);
    cudaFuncSetAttribute(mlp_kernel, cudaFuncAttributeMaxDynamicSharedMemorySize, MLP_SMEM);
    mlp_kernel<<<BT/16, 256, MLP_SMEM>>>(W1, b1, W2, b2, bs, out);
}

// round 13
// speedup vs baseline: 1.2650x; 1.0256x over previous
#include <cuda_runtime.h>
#include <cuda_bf16.h>
#include <cstdint>
#include <cstddef>

#define B_  4
#define T_  1024
#define F_  256
#define D_  128
#define BT  (B_*T_)
#define NC  64
#define CH  16

// single dynamic smem symbol shared by all kernels (cast per-kernel)
extern __shared__ unsigned char sm_raw[];

// ---------------- scratch (static device globals: no allocation allowed) ----------------
__device__ __align__(16) __nv_bfloat16 g_xhi[(size_t)BT*F_];   // LN output, bf16 high part
__device__ __align__(16) __nv_bfloat16 g_xlo[(size_t)BT*F_];   // LN output, bf16 low part
__device__ __align__(16) __nv_bfloat16 g_whi[(size_t)4*D_*F_]; // [bn][128][256] weights hi
__device__ __align__(16) __nv_bfloat16 g_wlo[(size_t)4*D_*F_]; // weights lo
__device__ float g_P[(size_t)BT*512];            // [row][ K(128) | Q(128) | V(128) | SP(128) ]
__device__ float g_kvsum[(size_t)B_*NC*D_*D_];   // chunk KV sums -> in-place exclusive prefix
__device__ float g_zsum[(size_t)B_*NC*D_];       // chunk K sums  -> in-place exclusive prefix
__device__ float g_attn[(size_t)BT*D_];          // num/den

__device__ __forceinline__ float phi(float v) { return v > 0.f ? v + 1.f : expf(v); }

// ---------------- 1) LayerNorm -> bf16 hi/lo (+ folded weight split) ----------------
__global__ void ln_kernel(const float* __restrict__ x,
                          const float* __restrict__ gamma,
                          const float* __restrict__ beta,
                          const float* __restrict__ Wk, const float* __restrict__ Wq,
                          const float* __restrict__ Wv, const float* __restrict__ Ws) {
    int row = blockIdx.x;
    int tid = threadIdx.x;

    // folded weight conversion: 4096 blocks x 8 elems = 32768 per matrix
    if (tid < 8) {
        int idx = blockIdx.x*8 + tid;
        const float* srcs[4] = {Wk, Wq, Wv, Ws};
        #pragma unroll
        for (int bn = 0; bn < 4; bn++) {
            float v = srcs[bn][idx];
            __nv_bfloat16 h = __float2bfloat16(v);
            __nv_bfloat16 l = __float2bfloat16(v - __bfloat162float(h));
            g_whi[(size_t)bn*32768 + idx] = h;
            g_wlo[(size_t)bn*32768 + idx] = l;
        }
    }

    float v = x[(size_t)row*F_ + tid];
    float s = v, s2 = v*v;
    #pragma unroll
    for (int o = 16; o; o >>= 1) {
        s  += __shfl_xor_sync(0xffffffffu, s,  o);
        s2 += __shfl_xor_sync(0xffffffffu, s2, o);
    }
    __shared__ float ss[8], ss2[8];
    int wid = tid >> 5, lane = tid & 31;
    if (lane == 0) { ss[wid] = s; ss2[wid] = s2; }
    __syncthreads();
    float ts = 0.f, ts2 = 0.f;
    #pragma unroll
    for (int i = 0; i < 8; i++) { ts += ss[i]; ts2 += ss2[i]; }
    float mu  = ts * (1.f/F_);
    float var = ts2 * (1.f/F_) - mu*mu;
    float r   = rsqrtf(var + 1e-5f);
    float xn  = (v - mu) * r * gamma[tid] + beta[tid];
    __nv_bfloat16 h = __float2bfloat16(xn);
    __nv_bfloat16 l = __float2bfloat16(xn - __bfloat162float(h));
    g_xhi[(size_t)row*F_ + tid] = h;
    g_xlo[(size_t)row*F_ + tid] = l;
}

// ---------------- 2) projection GEMM via split-bf16 HMMA ----------------
#define KSTG 64
#define ASTR 72
#define PJ_SMEM (4*128*ASTR*2)   // Ah, Al, Wh, Wl (bytes)

__device__ __forceinline__ void mma_bf16(float& c0, float& c1, float& c2, float& c3,
                                         uint32_t a0, uint32_t a1, uint32_t a2, uint32_t a3,
                                         uint32_t b0, uint32_t b1) {
    asm volatile("mma.sync.aligned.m16n8k16.row.col.f32.bf16.bf16.f32 "
                 "{%0,%1,%2,%3}, {%4,%5,%6,%7}, {%8,%9}, {%0,%1,%2,%3};"
                 : "+f"(c0), "+f"(c1), "+f"(c2), "+f"(c3)
                 : "r"(a0), "r"(a1), "r"(a2), "r"(a3), "r"(b0), "r"(b1));
}

__global__ void __launch_bounds__(256) proj_gemm_bf16() {
    __nv_bfloat16* Ah = (__nv_bfloat16*)sm_raw;
    __nv_bfloat16* Al = Ah + 128*ASTR;
    __nv_bfloat16* Wh = Al + 128*ASTR;
    __nv_bfloat16* Wl = Wh + 128*ASTR;

    const int bm = blockIdx.x, bn = blockIdx.y;
    const int tid = threadIdx.x;
    const int wid = tid >> 5, lane = tid & 31;
    const int warp_m = wid >> 2, warp_n = wid & 3;
    const int g  = lane >> 2;          // 0..7
    const int c2 = (lane & 3) * 2;     // 0,2,4,6

    const int lrow = tid >> 1;
    const int lcol = (tid & 1) * 32;

    float c[4][4][4];
    #pragma unroll
    for (int mt = 0; mt < 4; mt++)
        #pragma unroll
        for (int nt = 0; nt < 4; nt++)
            #pragma unroll
            for (int i = 0; i < 4; i++) c[mt][nt][i] = 0.f;

    const size_t arow = (size_t)(bm*128 + lrow)*F_;
    const size_t wrow = (size_t)bn*32768 + (size_t)lrow*F_;

    for (int k0 = 0; k0 < F_; k0 += KSTG) {
        #pragma unroll
        for (int j = 0; j < 4; j++) {
            int co = lcol + j*8;
            *(uint4*)&Ah[lrow*ASTR + co] = *(const uint4*)&g_xhi[arow + k0 + co];
            *(uint4*)&Al[lrow*ASTR + co] = *(const uint4*)&g_xlo[arow + k0 + co];
            *(uint4*)&Wh[lrow*ASTR + co] = *(const uint4*)&g_whi[wrow + k0 + co];
            *(uint4*)&Wl[lrow*ASTR + co] = *(const uint4*)&g_wlo[wrow + k0 + co];
        }
        __syncthreads();

        #pragma unroll
        for (int ks = 0; ks < KSTG/16; ks++) {
            const int kb = ks*16;
            uint32_t ah[4][4], al[4][4], bh[4][2], bl[4][2];
            #pragma unroll
            for (int mt = 0; mt < 4; mt++) {
                int r0 = warp_m*64 + mt*16 + g;
                ah[mt][0] = *(const uint32_t*)&Ah[ r0     *ASTR + kb + c2];
                ah[mt][1] = *(const uint32_t*)&Ah[(r0+8)  *ASTR + kb + c2];
                ah[mt][2] = *(const uint32_t*)&Ah[ r0     *ASTR + kb + 8 + c2];
                ah[mt][3] = *(const uint32_t*)&Ah[(r0+8)  *ASTR + kb + 8 + c2];
                al[mt][0] = *(const uint32_t*)&Al[ r0     *ASTR + kb + c2];
                al[mt][1] = *(const uint32_t*)&Al[(r0+8)  *ASTR + kb + c2];
                al[mt][2] = *(const uint32_t*)&Al[ r0     *ASTR + kb + 8 + c2];
                al[mt][3] = *(const uint32_t*)&Al[(r0+8)  *ASTR + kb + 8 + c2];
            }
            #pragma unroll
            for (int nt = 0; nt < 4; nt++) {
                int n = warp_n*32 + nt*8 + g;
                bh[nt][0] = *(const uint32_t*)&Wh[n*ASTR + kb + c2];
                bh[nt][1] = *(const uint32_t*)&Wh[n*ASTR + kb + 8 + c2];
                bl[nt][0] = *(const uint32_t*)&Wl[n*ASTR + kb + c2];
                bl[nt][1] = *(const uint32_t*)&Wl[n*ASTR + kb + 8 + c2];
            }
            #pragma unroll
            for (int mt = 0; mt < 4; mt++)
                #pragma unroll
                for (int nt = 0; nt < 4; nt++) {
                    float* cc = c[mt][nt];
                    mma_bf16(cc[0],cc[1],cc[2],cc[3], ah[mt][0],ah[mt][1],ah[mt][2],ah[mt][3], bh[nt][0],bh[nt][1]);
                    mma_bf16(cc[0],cc[1],cc[2],cc[3], ah[mt][0],ah[mt][1],ah[mt][2],ah[mt][3], bl[nt][0],bl[nt][1]);
                    mma_bf16(cc[0],cc[1],cc[2],cc[3], al[mt][0],al[mt][1],al[mt][2],al[mt][3], bh[nt][0],bh[nt][1]);
                }
        }
        __syncthreads();
    }

    const bool doPhi = (bn < 2);
    #pragma unroll
    for (int mt = 0; mt < 4; mt++) {
        #pragma unroll
        for (int nt = 0; nt < 4; nt++) {
            int row = bm*128 + warp_m*64 + mt*16 + g;
            int col = warp_n*32 + nt*8 + c2;
            float v0 = c[mt][nt][0], v1 = c[mt][nt][1];
            float v2 = c[mt][nt][2], v3 = c[mt][nt][3];
            if (doPhi) { v0 = phi(v0); v1 = phi(v1); v2 = phi(v2); v3 = phi(v3); }
            float* p0 = g_P + (size_t)row*512 + bn*128 + col;
            float* p1 = g_P + (size_t)(row+8)*512 + bn*128 + col;
            *(float2*)p0 = make_float2(v0, v1);
            *(float2*)p1 = make_float2(v2, v3);
        }
    }
}

// ---------------- 3) per-chunk KV sums + K sums (split over K-row halves) ----------------
// grid = B*NC*2 = 512; blk -> (b, c, half). Block computes S-rows [half*64, half*64+64).
__global__ void __launch_bounds__(256) chunksum_kernel() {
    int blk = blockIdx.x;
    int b = blk >> 7, c = (blk >> 1) & 63, half = blk & 1;
    __shared__ float Kc[CH][64], Vc[CH][D_];
    int tid = threadIdx.x, wid = tid >> 5, lane = tid & 31;
    int rowbase = b*T_ + c*CH;

    // Vc full width
    for (int i = tid; i < CH*32; i += 256) {
        int t = i >> 5, c4 = (i & 31) * 4;
        *(float4*)&Vc[t][c4] = *(const float4*)(g_P + (size_t)(rowbase + t)*512 + 256 + c4);
    }
    // Kc half width (this block's 64 K-rows)
    for (int i = tid; i < CH*16; i += 256) {
        int t = i >> 4, c4 = (i & 15) * 4;
        *(float4*)&Kc[t][c4] = *(const float4*)(g_P + (size_t)(rowbase + t)*512 + half*64 + c4);
    }
    __syncthreads();

    float4 acc[8];
    #pragma unroll
    for (int r = 0; r < 8; r++) acc[r] = make_float4(0.f,0.f,0.f,0.f);

    #pragma unroll
    for (int t = 0; t < CH; t++) {
        float4 v = *(const float4*)&Vc[t][lane*4];
        #pragma unroll
        for (int r = 0; r < 8; r++) {
            float k = Kc[t][wid + 8*r];
            acc[r].x += k*v.x; acc[r].y += k*v.y; acc[r].z += k*v.z; acc[r].w += k*v.w;
        }
    }
    size_t obase = ((size_t)(b*NC + c)*D_ + half*64 + wid)*D_ + lane*4;
    #pragma unroll
    for (int r = 0; r < 8; r++)
        *(float4*)&g_kvsum[obase + (size_t)r*8*D_] = acc[r];

    if (tid < 64) {
        float s = 0.f;
        #pragma unroll
        for (int t = 0; t < CH; t++) s += Kc[t][tid];
        g_zsum[(size_t)(b*NC + c)*D_ + half*64 + tid] = s;
    }
}

// ---------------- 4) fused exclusive prefix over chunks (S blocks 0-255, Z blocks 256-257) ----------------
__global__ void __launch_bounds__(256) prefix_kernel(const float* __restrict__ S0,
                                                     const float* __restrict__ Z0) {
    if (blockIdx.x < 256) {
        int gid = blockIdx.x*256 + threadIdx.x;  // B*D*D = 65536
        int b = gid >> 14, ij = gid & 16383;
        size_t base = (size_t)b*NC*16384 + ij;
        float acc = S0[(size_t)b*16384 + ij];

        float v[32];
        #pragma unroll
        for (int c = 0; c < 32; c++) v[c] = g_kvsum[base + (size_t)c*16384];
        #pragma unroll
        for (int c = 0; c < 32; c++) { float t = v[c]; v[c] = acc; acc += t; }
        #pragma unroll
        for (int c = 0; c < 32; c++) g_kvsum[base + (size_t)c*16384] = v[c];
        #pragma unroll
        for (int c = 0; c < 32; c++) v[c] = g_kvsum[base + (size_t)(c+32)*16384];
        #pragma unroll
        for (int c = 0; c < 32; c++) { float t = v[c]; v[c] = acc; acc += t; }
        #pragma unroll
        for (int c = 0; c < 32; c++) g_kvsum[base + (size_t)(c+32)*16384] = v[c];
    } else {
        int gid = (blockIdx.x - 256)*256 + threadIdx.x;  // B*D = 512
        int b = gid >> 7, i = gid & 127;
        float acc = Z0[b*128 + i];
        float v[NC];
        #pragma unroll
        for (int c = 0; c < NC; c++) v[c] = g_zsum[(size_t)(b*NC + c)*D_ + i];
        #pragma unroll
        for (int c = 0; c < NC; c++) { float t = v[c]; v[c] = acc; acc += t; }
        #pragma unroll
        for (int c = 0; c < NC; c++) g_zsum[(size_t)(b*NC + c)*D_ + i] = v[c];
    }
}

// ---------------- 5) main scan: S, Z, num, den, attn fused ----------------
__global__ void __launch_bounds__(256) scan_kernel(float* __restrict__ Sout,
                                                   float* __restrict__ Zout) {
    int blk = blockIdx.x;
    int b = blk >> 6, c = blk & 63;
    int tid = threadIdx.x, wid = tid >> 5, lane = tid & 31;

    __shared__ float Kc[CH][D_], Qc[CH][D_], Vc[CH][D_];
    __shared__ float partial[8][D_];
    __shared__ float sden[4];

    int rowbase = b*T_ + c*CH;
    for (int i = tid; i < CH*32; i += 256) {
        int t = i >> 5, c4 = (i & 31) * 4;
        const float* p = g_P + (size_t)(rowbase + t)*512;
        *(float4*)&Kc[t][c4] = *(const float4*)(p + c4);
        *(float4*)&Qc[t][c4] = *(const float4*)(p + 128 + c4);
        *(float4*)&Vc[t][c4] = *(const float4*)(p + 256 + c4);
    }

    float4 st[16];
    size_t pbase = ((size_t)(b*NC + c)*D_ + wid)*D_ + lane*4;
    #pragma unroll
    for (int r = 0; r < 16; r++)
        st[r] = *(const float4*)&g_kvsum[pbase + (size_t)r*8*D_];

    float zr = (tid < 128) ? g_zsum[(size_t)(b*NC + c)*D_ + tid] : 0.f;
    __syncthreads();

    for (int t = 0; t < CH; t++) {
        int rowt = rowbase + t;
        float4 v = *(const float4*)&Vc[t][lane*4];
        float4 pn = make_float4(0.f,0.f,0.f,0.f);
        float* sbase = Sout + ((size_t)rowt*D_ + wid)*D_ + lane*4;
        #pragma unroll
        for (int r = 0; r < 16; r++) {
            float k = Kc[t][wid + 8*r];
            st[r].x += k*v.x; st[r].y += k*v.y; st[r].z += k*v.z; st[r].w += k*v.w;
            *(float4*)(sbase + (size_t)r*8*D_) = st[r];
            float q = Qc[t][wid + 8*r];
            pn.x += q*st[r].x; pn.y += q*st[r].y; pn.z += q*st[r].z; pn.w += q*st[r].w;
        }
        *(float4*)&partial[wid][lane*4] = pn;
        __syncthreads();

        float numj = 0.f;
        if (tid < 128) {
            #pragma unroll
            for (int w = 0; w < 8; w++) numj += partial[w][tid];
            zr += Kc[t][tid];
            Zout[(size_t)rowt*D_ + tid] = zr;
            float dp = Qc[t][tid] * zr;
            #pragma unroll
            for (int o = 16; o; o >>= 1) dp += __shfl_xor_sync(0xffffffffu, dp, o);
            if (lane == 0) sden[wid] = dp;
        }
        __syncthreads();

        if (tid < 128) {
            float den = sden[0] + sden[1] + sden[2] + sden[3] + 1e-5f;
            g_attn[(size_t)rowt*D_ + tid] = numj / den;
        }
    }
}

// ---------------- 6) MLP tail ----------------
#define WPAD 132
#define MLP_SMEM ((128*WPAD + 16*128 + 16*128) * 4)

__global__ void __launch_bounds__(256) mlp_kernel(const float* __restrict__ W1,
                                                  const float* __restrict__ b1,
                                                  const float* __restrict__ W2,
                                                  const float* __restrict__ b2,
                                                  const float* __restrict__ bs,
                                                  float* __restrict__ out) {
    float* sW = (float*)sm_raw;
    float* sA = sW + 128*WPAD;
    float* sH = sA + 16*128;

    int tid = threadIdx.x;
    int r0  = blockIdx.x * 16;
    int e   = tid & 127;
    int rr  = (tid >> 7) * 8;

    for (int i = tid; i < 16*32; i += 256) {
        int r = i >> 5, c4 = (i & 31) * 4;
        *(float4*)&sA[r*128 + c4] = *(const float4*)(g_attn + (size_t)(r0 + r)*128 + c4);
    }
    #pragma unroll
    for (int rep = 0; rep < 16; rep++) {
        int i = rep*256 + tid;
        int ee = i >> 5, d4 = (i & 31) * 4;
        *(float4*)&sW[ee*WPAD + d4] = *(const float4*)(W1 + (size_t)ee*128 + d4);
    }
    __syncthreads();

    float acc[8];
    #pragma unroll
    for (int i = 0; i < 8; i++) acc[i] = 0.f;
    for (int d4 = 0; d4 < 128; d4 += 4) {
        float4 w = *(const float4*)&sW[e*WPAD + d4];
        #pragma unroll
        for (int i = 0; i < 8; i++) {
            float4 a = *(const float4*)&sA[(rr + i)*128 + d4];
            acc[i] += a.x*w.x + a.y*w.y + a.z*w.z + a.w*w.w;
        }
    }
    float bb1 = __ldg(&b1[e]);
    #pragma unroll
    for (int i = 0; i < 8; i++)
        sH[(rr + i)*128 + e] = fmaxf(acc[i] + bb1, 0.f);
    __syncthreads();

    #pragma unroll
    for (int rep = 0; rep < 16; rep++) {
        int i = rep*256 + tid;
        int ee = i >> 5, d4 = (i & 31) * 4;
        *(float4*)&sW[ee*WPAD + d4] = *(const float4*)(W2 + (size_t)ee*128 + d4);
    }
    __syncthreads();

    #pragma unroll
    for (int i = 0; i < 8; i++) acc[i] = 0.f;
    for (int d4 = 0; d4 < 128; d4 += 4) {
        float4 w = *(const float4*)&sW[e*WPAD + d4];
        #pragma unroll
        for (int i = 0; i < 8; i++) {
            float4 a = *(const float4*)&sH[(rr + i)*128 + d4];
            acc[i] += a.x*w.x + a.y*w.y + a.z*w.z + a.w*w.w;
        }
    }
    float bb2 = __ldg(&b2[e]);
    float bse = __ldg(&bs[e]);
    #pragma unroll
    for (int i = 0; i < 8; i++) {
        size_t row = (size_t)(r0 + rr + i);
        float sp = g_P[row*512 + 384 + e];
        out[row*128 + e] = fmaxf(acc[i] + bb2, 0.f) + sp + bse;
    }
}

// ---------------- launcher ----------------
extern "C" void kernel_launch(void* const* d_in, const int* in_sizes, int n_in,
                              void* d_out, int out_size) {
    const float* x    = (const float*)d_in[0];
    const float* S0   = (const float*)d_in[1];
    const float* Z0   = (const float*)d_in[2];
    const float* ln_g = (const float*)d_in[3];
    const float* ln_b = (const float*)d_in[4];
    const float* Wk   = (const float*)d_in[5];
    const float* Wq   = (const float*)d_in[6];
    const float* Wv   = (const float*)d_in[7];
    const float* W1   = (const float*)d_in[8];
    const float* b1   = (const float*)d_in[9];
    const float* W2   = (const float*)d_in[10];
    const float* b2   = (const float*)d_in[11];
    const float* Ws   = (const float*)d_in[12];
    const float* bs   = (const float*)d_in[13];

    float* out  = (float*)d_out;
    float* Sout = out  + (size_t)BT*D_;
    float* Zout = Sout + (size_t)BT*D_*D_;

    ln_kernel<<<BT, 256>>>(x, ln_g, ln_b, Wk, Wq, Wv, Ws);
    cudaFuncSetAttribute(proj_gemm_bf16, cudaFuncAttributeMaxDynamicSharedMemorySize, PJ_SMEM);
    proj_gemm_bf16<<<dim3(BT/128, 4), 256, PJ_SMEM>>>();
    chunksum_kernel<<<B_*NC*2, 256>>>();
    prefix_kernel<<<258, 256>>>(S0, Z0);
    scan_kernel<<<B_*NC, 256>>>(Sout, Zout);
    cudaFuncSetAttribute(mlp_kernel, cudaFuncAttributeMaxDynamicSharedMemorySize, MLP_SMEM);
    mlp_kernel<<<BT/16, 256, MLP_SMEM>>>(W1, b1, W2, b2, bs, out);
}

// round 14
// speedup vs baseline: 1.2839x; 1.0150x over previous
#include <cuda_runtime.h>
#include <cuda_bf16.h>
#include <cstdint>
#include <cstddef>

#define B_  4
#define T_  1024
#define F_  256
#define D_  128
#define BT  (B_*T_)
#define NC  64
#define CH  16

// single dynamic smem symbol shared by all kernels (cast per-kernel)
extern __shared__ unsigned char sm_raw[];

// ---------------- scratch (static device globals: no allocation allowed) ----------------
__device__ __align__(16) __nv_bfloat16 g_xhi[(size_t)BT*F_];   // LN output, bf16 high part
__device__ __align__(16) __nv_bfloat16 g_xlo[(size_t)BT*F_];   // LN output, bf16 low part
__device__ __align__(16) __nv_bfloat16 g_whi[(size_t)4*D_*F_]; // [bn][128][256] weights hi
__device__ __align__(16) __nv_bfloat16 g_wlo[(size_t)4*D_*F_]; // weights lo
__device__ float g_P[(size_t)BT*512];            // [row][ K(128) | Q(128) | V(128) | SP(128) ]
__device__ float g_kvsum[(size_t)B_*NC*D_*D_];   // chunk KV sums -> in-place exclusive prefix
__device__ float g_zsum[(size_t)B_*NC*D_];       // chunk K sums  -> in-place exclusive prefix

__device__ __forceinline__ float phi(float v) { return v > 0.f ? v + 1.f : expf(v); }

// ---------------- 1) LayerNorm -> bf16 hi/lo (+ folded weight split) ----------------
__global__ void ln_kernel(const float* __restrict__ x,
                          const float* __restrict__ gamma,
                          const float* __restrict__ beta,
                          const float* __restrict__ Wk, const float* __restrict__ Wq,
                          const float* __restrict__ Wv, const float* __restrict__ Ws) {
    int row = blockIdx.x;
    int tid = threadIdx.x;

    if (tid < 8) {
        int idx = blockIdx.x*8 + tid;
        const float* srcs[4] = {Wk, Wq, Wv, Ws};
        #pragma unroll
        for (int bn = 0; bn < 4; bn++) {
            float v = srcs[bn][idx];
            __nv_bfloat16 h = __float2bfloat16(v);
            __nv_bfloat16 l = __float2bfloat16(v - __bfloat162float(h));
            g_whi[(size_t)bn*32768 + idx] = h;
            g_wlo[(size_t)bn*32768 + idx] = l;
        }
    }

    float v = x[(size_t)row*F_ + tid];
    float s = v, s2 = v*v;
    #pragma unroll
    for (int o = 16; o; o >>= 1) {
        s  += __shfl_xor_sync(0xffffffffu, s,  o);
        s2 += __shfl_xor_sync(0xffffffffu, s2, o);
    }
    __shared__ float ss[8], ss2[8];
    int wid = tid >> 5, lane = tid & 31;
    if (lane == 0) { ss[wid] = s; ss2[wid] = s2; }
    __syncthreads();
    float ts = 0.f, ts2 = 0.f;
    #pragma unroll
    for (int i = 0; i < 8; i++) { ts += ss[i]; ts2 += ss2[i]; }
    float mu  = ts * (1.f/F_);
    float var = ts2 * (1.f/F_) - mu*mu;
    float r   = rsqrtf(var + 1e-5f);
    float xn  = (v - mu) * r * gamma[tid] + beta[tid];
    __nv_bfloat16 h = __float2bfloat16(xn);
    __nv_bfloat16 l = __float2bfloat16(xn - __bfloat162float(h));
    g_xhi[(size_t)row*F_ + tid] = h;
    g_xlo[(size_t)row*F_ + tid] = l;
}

// ---------------- 2) projection GEMM via split-bf16 HMMA ----------------
#define KSTG 64
#define ASTR 72
#define PJ_SMEM (4*128*ASTR*2)   // Ah, Al, Wh, Wl (bytes)

__device__ __forceinline__ void mma_bf16(float& c0, float& c1, float& c2, float& c3,
                                         uint32_t a0, uint32_t a1, uint32_t a2, uint32_t a3,
                                         uint32_t b0, uint32_t b1) {
    asm volatile("mma.sync.aligned.m16n8k16.row.col.f32.bf16.bf16.f32 "
                 "{%0,%1,%2,%3}, {%4,%5,%6,%7}, {%8,%9}, {%0,%1,%2,%3};"
                 : "+f"(c0), "+f"(c1), "+f"(c2), "+f"(c3)
                 : "r"(a0), "r"(a1), "r"(a2), "r"(a3), "r"(b0), "r"(b1));
}

__global__ void __launch_bounds__(256) proj_gemm_bf16() {
    __nv_bfloat16* Ah = (__nv_bfloat16*)sm_raw;
    __nv_bfloat16* Al = Ah + 128*ASTR;
    __nv_bfloat16* Wh = Al + 128*ASTR;
    __nv_bfloat16* Wl = Wh + 128*ASTR;

    const int bm = blockIdx.x, bn = blockIdx.y;
    const int tid = threadIdx.x;
    const int wid = tid >> 5, lane = tid & 31;
    const int warp_m = wid >> 2, warp_n = wid & 3;
    const int g  = lane >> 2;          // 0..7
    const int c2 = (lane & 3) * 2;     // 0,2,4,6

    const int lrow = tid >> 1;
    const int lcol = (tid & 1) * 32;

    float c[4][4][4];
    #pragma unroll
    for (int mt = 0; mt < 4; mt++)
        #pragma unroll
        for (int nt = 0; nt < 4; nt++)
            #pragma unroll
            for (int i = 0; i < 4; i++) c[mt][nt][i] = 0.f;

    const size_t arow = (size_t)(bm*128 + lrow)*F_;
    const size_t wrow = (size_t)bn*32768 + (size_t)lrow*F_;

    for (int k0 = 0; k0 < F_; k0 += KSTG) {
        #pragma unroll
        for (int j = 0; j < 4; j++) {
            int co = lcol + j*8;
            *(uint4*)&Ah[lrow*ASTR + co] = *(const uint4*)&g_xhi[arow + k0 + co];
            *(uint4*)&Al[lrow*ASTR + co] = *(const uint4*)&g_xlo[arow + k0 + co];
            *(uint4*)&Wh[lrow*ASTR + co] = *(const uint4*)&g_whi[wrow + k0 + co];
            *(uint4*)&Wl[lrow*ASTR + co] = *(const uint4*)&g_wlo[wrow + k0 + co];
        }
        __syncthreads();

        #pragma unroll
        for (int ks = 0; ks < KSTG/16; ks++) {
            const int kb = ks*16;
            uint32_t ah[4][4], al[4][4], bh[4][2], bl[4][2];
            #pragma unroll
            for (int mt = 0; mt < 4; mt++) {
                int r0 = warp_m*64 + mt*16 + g;
                ah[mt][0] = *(const uint32_t*)&Ah[ r0     *ASTR + kb + c2];
                ah[mt][1] = *(const uint32_t*)&Ah[(r0+8)  *ASTR + kb + c2];
                ah[mt][2] = *(const uint32_t*)&Ah[ r0     *ASTR + kb + 8 + c2];
                ah[mt][3] = *(const uint32_t*)&Ah[(r0+8)  *ASTR + kb + 8 + c2];
                al[mt][0] = *(const uint32_t*)&Al[ r0     *ASTR + kb + c2];
                al[mt][1] = *(const uint32_t*)&Al[(r0+8)  *ASTR + kb + c2];
                al[mt][2] = *(const uint32_t*)&Al[ r0     *ASTR + kb + 8 + c2];
                al[mt][3] = *(const uint32_t*)&Al[(r0+8)  *ASTR + kb + 8 + c2];
            }
            #pragma unroll
            for (int nt = 0; nt < 4; nt++) {
                int n = warp_n*32 + nt*8 + g;
                bh[nt][0] = *(const uint32_t*)&Wh[n*ASTR + kb + c2];
                bh[nt][1] = *(const uint32_t*)&Wh[n*ASTR + kb + 8 + c2];
                bl[nt][0] = *(const uint32_t*)&Wl[n*ASTR + kb + c2];
                bl[nt][1] = *(const uint32_t*)&Wl[n*ASTR + kb + 8 + c2];
            }
            #pragma unroll
            for (int mt = 0; mt < 4; mt++)
                #pragma unroll
                for (int nt = 0; nt < 4; nt++) {
                    float* cc = c[mt][nt];
                    mma_bf16(cc[0],cc[1],cc[2],cc[3], ah[mt][0],ah[mt][1],ah[mt][2],ah[mt][3], bh[nt][0],bh[nt][1]);
                    mma_bf16(cc[0],cc[1],cc[2],cc[3], ah[mt][0],ah[mt][1],ah[mt][2],ah[mt][3], bl[nt][0],bl[nt][1]);
                    mma_bf16(cc[0],cc[1],cc[2],cc[3], al[mt][0],al[mt][1],al[mt][2],al[mt][3], bh[nt][0],bh[nt][1]);
                }
        }
        __syncthreads();
    }

    const bool doPhi = (bn < 2);
    #pragma unroll
    for (int mt = 0; mt < 4; mt++) {
        #pragma unroll
        for (int nt = 0; nt < 4; nt++) {
            int row = bm*128 + warp_m*64 + mt*16 + g;
            int col = warp_n*32 + nt*8 + c2;
            float v0 = c[mt][nt][0], v1 = c[mt][nt][1];
            float v2 = c[mt][nt][2], v3 = c[mt][nt][3];
            if (doPhi) { v0 = phi(v0); v1 = phi(v1); v2 = phi(v2); v3 = phi(v3); }
            float* p0 = g_P + (size_t)row*512 + bn*128 + col;
            float* p1 = g_P + (size_t)(row+8)*512 + bn*128 + col;
            *(float2*)p0 = make_float2(v0, v1);
            *(float2*)p1 = make_float2(v2, v3);
        }
    }
}

// ---------------- 3) per-chunk KV sums + K sums (split over K-row halves) ----------------
__global__ void __launch_bounds__(256) chunksum_kernel() {
    int blk = blockIdx.x;
    int b = blk >> 7, c = (blk >> 1) & 63, half = blk & 1;
    __shared__ float Kc[CH][64], Vc[CH][D_];
    int tid = threadIdx.x, wid = tid >> 5, lane = tid & 31;
    int rowbase = b*T_ + c*CH;

    for (int i = tid; i < CH*32; i += 256) {
        int t = i >> 5, c4 = (i & 31) * 4;
        *(float4*)&Vc[t][c4] = *(const float4*)(g_P + (size_t)(rowbase + t)*512 + 256 + c4);
    }
    for (int i = tid; i < CH*16; i += 256) {
        int t = i >> 4, c4 = (i & 15) * 4;
        *(float4*)&Kc[t][c4] = *(const float4*)(g_P + (size_t)(rowbase + t)*512 + half*64 + c4);
    }
    __syncthreads();

    float4 acc[8];
    #pragma unroll
    for (int r = 0; r < 8; r++) acc[r] = make_float4(0.f,0.f,0.f,0.f);

    #pragma unroll
    for (int t = 0; t < CH; t++) {
        float4 v = *(const float4*)&Vc[t][lane*4];
        #pragma unroll
        for (int r = 0; r < 8; r++) {
            float k = Kc[t][wid + 8*r];
            acc[r].x += k*v.x; acc[r].y += k*v.y; acc[r].z += k*v.z; acc[r].w += k*v.w;
        }
    }
    size_t obase = ((size_t)(b*NC + c)*D_ + half*64 + wid)*D_ + lane*4;
    #pragma unroll
    for (int r = 0; r < 8; r++)
        *(float4*)&g_kvsum[obase + (size_t)r*8*D_] = acc[r];

    if (tid < 64) {
        float s = 0.f;
        #pragma unroll
        for (int t = 0; t < CH; t++) s += Kc[t][tid];
        g_zsum[(size_t)(b*NC + c)*D_ + half*64 + tid] = s;
    }
}

// ---------------- 4) exclusive prefix: split-serial halves (S blocks 0-511, Z blocks 512-513) ----------------
__global__ void __launch_bounds__(256) prefix_kernel(const float* __restrict__ S0,
                                                     const float* __restrict__ Z0) {
    __shared__ float tot[128];
    int tid = threadIdx.x;
    if (blockIdx.x < 512) {
        int lij = tid & 127, h = tid >> 7;
        int gij = blockIdx.x*128 + lij;              // 0..65535 = B*D*D
        int b = gij >> 14, ij = gij & 16383;
        size_t base = (size_t)b*NC*16384 + ij + (size_t)h*32*16384;

        float v[32];
        #pragma unroll
        for (int c = 0; c < 32; c++) v[c] = g_kvsum[base + (size_t)c*16384];
        float acc = (h == 0) ? S0[(size_t)b*16384 + ij] : 0.f;
        #pragma unroll
        for (int c = 0; c < 32; c++) { float t = v[c]; v[c] = acc; acc += t; }
        if (h == 0) tot[lij] = acc;                  // inclusive sum of first half (incl. S0)
        __syncthreads();
        float off = (h == 1) ? tot[lij] : 0.f;
        #pragma unroll
        for (int c = 0; c < 32; c++) g_kvsum[base + (size_t)c*16384] = v[c] + off;
    } else {
        int gid = (blockIdx.x - 512)*256 + tid;      // B*D = 512
        int b = gid >> 7, i = gid & 127;
        float acc = Z0[b*128 + i];
        float v[NC];
        #pragma unroll
        for (int c = 0; c < NC; c++) v[c] = g_zsum[(size_t)(b*NC + c)*D_ + i];
        #pragma unroll
        for (int c = 0; c < NC; c++) { float t = v[c]; v[c] = acc; acc += t; }
        #pragma unroll
        for (int c = 0; c < NC; c++) g_zsum[(size_t)(b*NC + c)*D_ + i] = v[c];
    }
}

// ---------------- 5) fused scan + MLP: S, Z, num, den, attn, MLP, residual ----------------
// smem (floats): Kc 2048 | Qc 2048 | Vc 2048 | partial 16384 | Zs 2048 | sden 16
// phase D reuses: sW = partial..partial+18432(incl Zs), sH = Kc..(+Qc), As = Vc.
#define WPAD 132
#define SC_SMEM ((2048*3 + 16384 + 2048 + 16) * 4)

__global__ void __launch_bounds__(256) scan_kernel(const float* __restrict__ W1,
                                                   const float* __restrict__ b1,
                                                   const float* __restrict__ W2,
                                                   const float* __restrict__ b2,
                                                   const float* __restrict__ bs,
                                                   float* __restrict__ out,
                                                   float* __restrict__ Sout,
                                                   float* __restrict__ Zout) {
    float* Kc      = (float*)sm_raw;       // [16][128]
    float* Qc      = Kc + 2048;            // [16][128]
    float* Vc      = Qc + 2048;            // [16][128]
    float* partial = Vc + 2048;            // [8][16][128]
    float* Zs      = partial + 16384;      // [16][128]
    float* sden    = Zs + 2048;            // [16]

    int blk = blockIdx.x;
    int b = blk >> 6, c = blk & 63;
    int tid = threadIdx.x, wid = tid >> 5, lane = tid & 31;
    int rowbase = b*T_ + c*CH;

    for (int i = tid; i < CH*32; i += 256) {
        int t = i >> 5, c4 = (i & 31) * 4;
        const float* p = g_P + (size_t)(rowbase + t)*512;
        *(float4*)&Kc[t*128 + c4] = *(const float4*)(p + c4);
        *(float4*)&Qc[t*128 + c4] = *(const float4*)(p + 128 + c4);
        *(float4*)&Vc[t*128 + c4] = *(const float4*)(p + 256 + c4);
    }

    float4 st[16];
    size_t pbase = ((size_t)(b*NC + c)*D_ + wid)*D_ + lane*4;
    #pragma unroll
    for (int r = 0; r < 16; r++)
        st[r] = *(const float4*)&g_kvsum[pbase + (size_t)r*8*D_];
    __syncthreads();

    // ---- main loop: NO barriers ----
    for (int t = 0; t < CH; t++) {
        float4 v = *(const float4*)&Vc[t*128 + lane*4];
        float4 pn = make_float4(0.f,0.f,0.f,0.f);
        float* sbase = Sout + ((size_t)(rowbase + t)*D_ + wid)*D_ + lane*4;
        #pragma unroll
        for (int r = 0; r < 16; r++) {
            float k = Kc[t*128 + wid + 8*r];
            st[r].x += k*v.x; st[r].y += k*v.y; st[r].z += k*v.z; st[r].w += k*v.w;
            *(float4*)(sbase + (size_t)r*8*D_) = st[r];
            float q = Qc[t*128 + wid + 8*r];
            pn.x += q*st[r].x; pn.y += q*st[r].y; pn.z += q*st[r].z; pn.w += q*st[r].w;
        }
        *(float4*)&partial[wid*2048 + t*128 + lane*4] = pn;
    }

    // ---- phase A: Z prefix within chunk ----
    if (tid < 128) {
        float zr = g_zsum[(size_t)(b*NC + c)*D_ + tid];
        #pragma unroll
        for (int t = 0; t < CH; t++) {
            zr += Kc[t*128 + tid];
            Zs[t*128 + tid] = zr;
            Zout[(size_t)(rowbase + t)*D_ + tid] = zr;
        }
    }
    __syncthreads();

    // ---- phase B: den[t] = Q[t] . Z[t]  (warp w -> tokens 2w, 2w+1) ----
    #pragma unroll
    for (int s = 0; s < 2; s++) {
        int t = wid*2 + s;
        float dp = 0.f;
        #pragma unroll
        for (int jj = 0; jj < 4; jj++) {
            int j = lane + jj*32;
            dp += Qc[t*128 + j] * Zs[t*128 + j];
        }
        #pragma unroll
        for (int o = 16; o; o >>= 1) dp += __shfl_xor_sync(0xffffffffu, dp, o);
        if (lane == 0) sden[t] = dp;
    }
    __syncthreads();

    // ---- phase C: attn -> As (reuse Vc) ----
    float* As = Vc;
    #pragma unroll
    for (int k = 0; k < 8; k++) {
        int idx = tid + k*256;       // 0..2047
        int t = idx >> 7, j = idx & 127;
        float num = 0.f;
        #pragma unroll
        for (int w = 0; w < 8; w++) num += partial[w*2048 + t*128 + j];
        As[t*128 + j] = num / (sden[t] + 1e-5f);
    }
    __syncthreads();

    // ---- phase D: MLP on 16 rows (sW reuses partial+Zs, sH reuses Kc+Qc) ----
    float* sW = partial;     // needs 128*WPAD = 16896 <= 18432 floats
    float* sH = Kc;          // needs 2048 <= 4096 floats

    int e  = tid & 127;
    int rr = (tid >> 7) * 8;

    #pragma unroll
    for (int rep = 0; rep < 16; rep++) {
        int i = rep*256 + tid;
        int ee = i >> 5, d4 = (i & 31) * 4;
        *(float4*)&sW[ee*WPAD + d4] = *(const float4*)(W1 + (size_t)ee*128 + d4);
    }
    __syncthreads();

    float acc[8];
    #pragma unroll
    for (int i = 0; i < 8; i++) acc[i] = 0.f;
    for (int d4 = 0; d4 < 128; d4 += 4) {
        float4 w = *(const float4*)&sW[e*WPAD + d4];
        #pragma unroll
        for (int i = 0; i < 8; i++) {
            float4 a = *(const float4*)&As[(rr + i)*128 + d4];
            acc[i] += a.x*w.x + a.y*w.y + a.z*w.z + a.w*w.w;
        }
    }
    float bb1 = __ldg(&b1[e]);
    #pragma unroll
    for (int i = 0; i < 8; i++)
        sH[(rr + i)*128 + e] = fmaxf(acc[i] + bb1, 0.f);
    __syncthreads();

    #pragma unroll
    for (int rep = 0; rep < 16; rep++) {
        int i = rep*256 + tid;
        int ee = i >> 5, d4 = (i & 31) * 4;
        *(float4*)&sW[ee*WPAD + d4] = *(const float4*)(W2 + (size_t)ee*128 + d4);
    }
    __syncthreads();

    #pragma unroll
    for (int i = 0; i < 8; i++) acc[i] = 0.f;
    for (int d4 = 0; d4 < 128; d4 += 4) {
        float4 w = *(const float4*)&sW[e*WPAD + d4];
        #pragma unroll
        for (int i = 0; i < 8; i++) {
            float4 a = *(const float4*)&sH[(rr + i)*128 + d4];
            acc[i] += a.x*w.x + a.y*w.y + a.z*w.z + a.w*w.w;
        }
    }
    float bb2 = __ldg(&b2[e]);
    float bse = __ldg(&bs[e]);
    #pragma unroll
    for (int i = 0; i < 8; i++) {
        size_t row = (size_t)(rowbase + rr + i);
        float sp = g_P[row*512 + 384 + e];
        out[row*128 + e] = fmaxf(acc[i] + bb2, 0.f) + sp + bse;
    }
}

// ---------------- launcher ----------------
extern "C" void kernel_launch(void* const* d_in, const int* in_sizes, int n_in,
                              void* d_out, int out_size) {
    const float* x    = (const float*)d_in[0];
    const float* S0   = (const float*)d_in[1];
    const float* Z0   = (const float*)d_in[2];
    const float* ln_g = (const float*)d_in[3];
    const float* ln_b = (const float*)d_in[4];
    const float* Wk   = (const float*)d_in[5];
    const float* Wq   = (const float*)d_in[6];
    const float* Wv   = (const float*)d_in[7];
    const float* W1   = (const float*)d_in[8];
    const float* b1   = (const float*)d_in[9];
    const float* W2   = (const float*)d_in[10];
    const float* b2   = (const float*)d_in[11];
    const float* Ws   = (const float*)d_in[12];
    const float* bs   = (const float*)d_in[13];

    float* out  = (float*)d_out;
    float* Sout = out  + (size_t)BT*D_;
    float* Zout = Sout + (size_t)BT*D_*D_;

    ln_kernel<<<BT, 256>>>(x, ln_g, ln_b, Wk, Wq, Wv, Ws);
    cudaFuncSetAttribute(proj_gemm_bf16, cudaFuncAttributeMaxDynamicSharedMemorySize, PJ_SMEM);
    proj_gemm_bf16<<<dim3(BT/128, 4), 256, PJ_SMEM>>>();
    chunksum_kernel<<<B_*NC*2, 256>>>();
    prefix_kernel<<<514, 256>>>(S0, Z0);
    cudaFuncSetAttribute(scan_kernel, cudaFuncAttributeMaxDynamicSharedMemorySize, SC_SMEM);
    scan_kernel<<<B_*NC, 256, SC_SMEM>>>(W1, b1, W2, b2, bs, out, Sout, Zout);
}

// round 15
// speedup vs baseline: 1.3695x; 1.0667x over previous
#include <cuda_runtime.h>
#include <cuda_bf16.h>
#include <cstdint>
#include <cstddef>

#define B_  4
#define T_  1024
#define F_  256
#define D_  128
#define BT  (B_*T_)
#define NC  64
#define CH  16

// single dynamic smem symbol shared by all kernels (cast per-kernel)
extern __shared__ unsigned char sm_raw[];

// ---------------- scratch (static device globals: no allocation allowed) ----------------
__device__ __align__(16) __nv_bfloat16 g_xhi[(size_t)BT*F_];   // LN output, bf16 high part
__device__ __align__(16) __nv_bfloat16 g_xlo[(size_t)BT*F_];   // LN output, bf16 low part
__device__ __align__(16) __nv_bfloat16 g_whi[(size_t)4*D_*F_]; // [bn][128][256] weights hi
__device__ __align__(16) __nv_bfloat16 g_wlo[(size_t)4*D_*F_]; // weights lo
__device__ float g_P[(size_t)BT*512];            // [row][ K(128) | Q(128) | V(128) | SP(128) ]
__device__ float g_kvsum[(size_t)B_*NC*D_*D_];   // chunk KV sums -> in-place exclusive prefix
__device__ float g_zsum[(size_t)B_*NC*D_];       // chunk K sums  -> in-place exclusive prefix

__device__ __forceinline__ float phi(float v) { return v > 0.f ? v + 1.f : expf(v); }

// ---------------- 1) LayerNorm -> bf16 hi/lo (+ folded weight split) ----------------
__global__ void ln_kernel(const float* __restrict__ x,
                          const float* __restrict__ gamma,
                          const float* __restrict__ beta,
                          const float* __restrict__ Wk, const float* __restrict__ Wq,
                          const float* __restrict__ Wv, const float* __restrict__ Ws) {
    int row = blockIdx.x;
    int tid = threadIdx.x;

    if (tid < 8) {
        int idx = blockIdx.x*8 + tid;
        const float* srcs[4] = {Wk, Wq, Wv, Ws};
        #pragma unroll
        for (int bn = 0; bn < 4; bn++) {
            float v = srcs[bn][idx];
            __nv_bfloat16 h = __float2bfloat16(v);
            __nv_bfloat16 l = __float2bfloat16(v - __bfloat162float(h));
            g_whi[(size_t)bn*32768 + idx] = h;
            g_wlo[(size_t)bn*32768 + idx] = l;
        }
    }

    float v = x[(size_t)row*F_ + tid];
    float s = v, s2 = v*v;
    #pragma unroll
    for (int o = 16; o; o >>= 1) {
        s  += __shfl_xor_sync(0xffffffffu, s,  o);
        s2 += __shfl_xor_sync(0xffffffffu, s2, o);
    }
    __shared__ float ss[8], ss2[8];
    int wid = tid >> 5, lane = tid & 31;
    if (lane == 0) { ss[wid] = s; ss2[wid] = s2; }
    __syncthreads();
    float ts = 0.f, ts2 = 0.f;
    #pragma unroll
    for (int i = 0; i < 8; i++) { ts += ss[i]; ts2 += ss2[i]; }
    float mu  = ts * (1.f/F_);
    float var = ts2 * (1.f/F_) - mu*mu;
    float r   = rsqrtf(var + 1e-5f);
    float xn  = (v - mu) * r * gamma[tid] + beta[tid];
    __nv_bfloat16 h = __float2bfloat16(xn);
    __nv_bfloat16 l = __float2bfloat16(xn - __bfloat162float(h));
    g_xhi[(size_t)row*F_ + tid] = h;
    g_xlo[(size_t)row*F_ + tid] = l;
}

// ---------------- 2) projection GEMM via split-bf16 HMMA ----------------
#define KSTG 64
#define ASTR 72
#define PJ_SMEM (4*128*ASTR*2)   // Ah, Al, Wh, Wl (bytes)

__device__ __forceinline__ void mma_bf16(float& c0, float& c1, float& c2, float& c3,
                                         uint32_t a0, uint32_t a1, uint32_t a2, uint32_t a3,
                                         uint32_t b0, uint32_t b1) {
    asm volatile("mma.sync.aligned.m16n8k16.row.col.f32.bf16.bf16.f32 "
                 "{%0,%1,%2,%3}, {%4,%5,%6,%7}, {%8,%9}, {%0,%1,%2,%3};"
                 : "+f"(c0), "+f"(c1), "+f"(c2), "+f"(c3)
                 : "r"(a0), "r"(a1), "r"(a2), "r"(a3), "r"(b0), "r"(b1));
}

__global__ void __launch_bounds__(256) proj_gemm_bf16() {
    __nv_bfloat16* Ah = (__nv_bfloat16*)sm_raw;
    __nv_bfloat16* Al = Ah + 128*ASTR;
    __nv_bfloat16* Wh = Al + 128*ASTR;
    __nv_bfloat16* Wl = Wh + 128*ASTR;

    const int bm = blockIdx.x, bn = blockIdx.y;
    const int tid = threadIdx.x;
    const int wid = tid >> 5, lane = tid & 31;
    const int warp_m = wid >> 2, warp_n = wid & 3;
    const int g  = lane >> 2;          // 0..7
    const int c2 = (lane & 3) * 2;     // 0,2,4,6

    const int lrow = tid >> 1;
    const int lcol = (tid & 1) * 32;

    float c[4][4][4];
    #pragma unroll
    for (int mt = 0; mt < 4; mt++)
        #pragma unroll
        for (int nt = 0; nt < 4; nt++)
            #pragma unroll
            for (int i = 0; i < 4; i++) c[mt][nt][i] = 0.f;

    const size_t arow = (size_t)(bm*128 + lrow)*F_;
    const size_t wrow = (size_t)bn*32768 + (size_t)lrow*F_;

    for (int k0 = 0; k0 < F_; k0 += KSTG) {
        #pragma unroll
        for (int j = 0; j < 4; j++) {
            int co = lcol + j*8;
            *(uint4*)&Ah[lrow*ASTR + co] = *(const uint4*)&g_xhi[arow + k0 + co];
            *(uint4*)&Al[lrow*ASTR + co] = *(const uint4*)&g_xlo[arow + k0 + co];
            *(uint4*)&Wh[lrow*ASTR + co] = *(const uint4*)&g_whi[wrow + k0 + co];
            *(uint4*)&Wl[lrow*ASTR + co] = *(const uint4*)&g_wlo[wrow + k0 + co];
        }
        __syncthreads();

        #pragma unroll
        for (int ks = 0; ks < KSTG/16; ks++) {
            const int kb = ks*16;
            uint32_t ah[4][4], al[4][4], bh[4][2], bl[4][2];
            #pragma unroll
            for (int mt = 0; mt < 4; mt++) {
                int r0 = warp_m*64 + mt*16 + g;
                ah[mt][0] = *(const uint32_t*)&Ah[ r0     *ASTR + kb + c2];
                ah[mt][1] = *(const uint32_t*)&Ah[(r0+8)  *ASTR + kb + c2];
                ah[mt][2] = *(const uint32_t*)&Ah[ r0     *ASTR + kb + 8 + c2];
                ah[mt][3] = *(const uint32_t*)&Ah[(r0+8)  *ASTR + kb + 8 + c2];
                al[mt][0] = *(const uint32_t*)&Al[ r0     *ASTR + kb + c2];
                al[mt][1] = *(const uint32_t*)&Al[(r0+8)  *ASTR + kb + c2];
                al[mt][2] = *(const uint32_t*)&Al[ r0     *ASTR + kb + 8 + c2];
                al[mt][3] = *(const uint32_t*)&Al[(r0+8)  *ASTR + kb + 8 + c2];
            }
            #pragma unroll
            for (int nt = 0; nt < 4; nt++) {
                int n = warp_n*32 + nt*8 + g;
                bh[nt][0] = *(const uint32_t*)&Wh[n*ASTR + kb + c2];
                bh[nt][1] = *(const uint32_t*)&Wh[n*ASTR + kb + 8 + c2];
                bl[nt][0] = *(const uint32_t*)&Wl[n*ASTR + kb + c2];
                bl[nt][1] = *(const uint32_t*)&Wl[n*ASTR + kb + 8 + c2];
            }
            #pragma unroll
            for (int mt = 0; mt < 4; mt++)
                #pragma unroll
                for (int nt = 0; nt < 4; nt++) {
                    float* cc = c[mt][nt];
                    mma_bf16(cc[0],cc[1],cc[2],cc[3], ah[mt][0],ah[mt][1],ah[mt][2],ah[mt][3], bh[nt][0],bh[nt][1]);
                    mma_bf16(cc[0],cc[1],cc[2],cc[3], ah[mt][0],ah[mt][1],ah[mt][2],ah[mt][3], bl[nt][0],bl[nt][1]);
                    mma_bf16(cc[0],cc[1],cc[2],cc[3], al[mt][0],al[mt][1],al[mt][2],al[mt][3], bh[nt][0],bh[nt][1]);
                }
        }
        __syncthreads();
    }

    const bool doPhi = (bn < 2);
    #pragma unroll
    for (int mt = 0; mt < 4; mt++) {
        #pragma unroll
        for (int nt = 0; nt < 4; nt++) {
            int row = bm*128 + warp_m*64 + mt*16 + g;
            int col = warp_n*32 + nt*8 + c2;
            float v0 = c[mt][nt][0], v1 = c[mt][nt][1];
            float v2 = c[mt][nt][2], v3 = c[mt][nt][3];
            if (doPhi) { v0 = phi(v0); v1 = phi(v1); v2 = phi(v2); v3 = phi(v3); }
            float* p0 = g_P + (size_t)row*512 + bn*128 + col;
            float* p1 = g_P + (size_t)(row+8)*512 + bn*128 + col;
            *(float2*)p0 = make_float2(v0, v1);
            *(float2*)p1 = make_float2(v2, v3);
        }
    }
}

// ---------------- 3) per-chunk KV sums + K sums (split over K-row halves) ----------------
__global__ void __launch_bounds__(256) chunksum_kernel() {
    int blk = blockIdx.x;
    int b = blk >> 7, c = (blk >> 1) & 63, half = blk & 1;
    __shared__ float Kc[CH][64], Vc[CH][D_];
    int tid = threadIdx.x, wid = tid >> 5, lane = tid & 31;
    int rowbase = b*T_ + c*CH;

    for (int i = tid; i < CH*32; i += 256) {
        int t = i >> 5, c4 = (i & 31) * 4;
        *(float4*)&Vc[t][c4] = *(const float4*)(g_P + (size_t)(rowbase + t)*512 + 256 + c4);
    }
    for (int i = tid; i < CH*16; i += 256) {
        int t = i >> 4, c4 = (i & 15) * 4;
        *(float4*)&Kc[t][c4] = *(const float4*)(g_P + (size_t)(rowbase + t)*512 + half*64 + c4);
    }
    __syncthreads();

    float4 acc[8];
    #pragma unroll
    for (int r = 0; r < 8; r++) acc[r] = make_float4(0.f,0.f,0.f,0.f);

    #pragma unroll
    for (int t = 0; t < CH; t++) {
        float4 v = *(const float4*)&Vc[t][lane*4];
        #pragma unroll
        for (int r = 0; r < 8; r++) {
            float k = Kc[t][wid + 8*r];
            acc[r].x += k*v.x; acc[r].y += k*v.y; acc[r].z += k*v.z; acc[r].w += k*v.w;
        }
    }
    size_t obase = ((size_t)(b*NC + c)*D_ + half*64 + wid)*D_ + lane*4;
    #pragma unroll
    for (int r = 0; r < 8; r++)
        *(float4*)&g_kvsum[obase + (size_t)r*8*D_] = acc[r];

    if (tid < 64) {
        float s = 0.f;
        #pragma unroll
        for (int t = 0; t < CH; t++) s += Kc[t][tid];
        g_zsum[(size_t)(b*NC + c)*D_ + half*64 + tid] = s;
    }
}

// ---------------- 4) exclusive prefix: single-thread chain, 64-wide front batch ----------------
__global__ void __launch_bounds__(256) prefix_kernel(const float* __restrict__ S0,
                                                     const float* __restrict__ Z0) {
    int tid = threadIdx.x;
    if (blockIdx.x < 256) {
        int gid = blockIdx.x*256 + tid;              // B*D*D = 65536
        int b = gid >> 14, ij = gid & 16383;
        size_t base = (size_t)b*NC*16384 + ij;

        float v[64];
        #pragma unroll
        for (int c = 0; c < 64; c++) v[c] = g_kvsum[base + (size_t)c*16384];
        float acc = S0[(size_t)b*16384 + ij];
        #pragma unroll
        for (int c = 0; c < 64; c++) { float t = v[c]; v[c] = acc; acc += t; }
        #pragma unroll
        for (int c = 0; c < 64; c++) g_kvsum[base + (size_t)c*16384] = v[c];
    } else {
        int gid = (blockIdx.x - 256)*256 + tid;      // B*D = 512
        int b = gid >> 7, i = gid & 127;
        float acc = Z0[b*128 + i];
        float v[NC];
        #pragma unroll
        for (int c = 0; c < NC; c++) v[c] = g_zsum[(size_t)(b*NC + c)*D_ + i];
        #pragma unroll
        for (int c = 0; c < NC; c++) { float t = v[c]; v[c] = acc; acc += t; }
        #pragma unroll
        for (int c = 0; c < NC; c++) g_zsum[(size_t)(b*NC + c)*D_ + i] = v[c];
    }
}

// ---------------- 5) fused scan + MLP: S, Z, num, den, attn, MLP, residual ----------------
#define WPAD 132
#define SC_SMEM ((2048*3 + 16384 + 2048 + 16) * 4)

__global__ void __launch_bounds__(256) scan_kernel(const float* __restrict__ W1,
                                                   const float* __restrict__ b1,
                                                   const float* __restrict__ W2,
                                                   const float* __restrict__ b2,
                                                   const float* __restrict__ bs,
                                                   float* __restrict__ out,
                                                   float* __restrict__ Sout,
                                                   float* __restrict__ Zout) {
    float* Kc      = (float*)sm_raw;       // [16][128]
    float* Qc      = Kc + 2048;            // [16][128]
    float* Vc      = Qc + 2048;            // [16][128]
    float* partial = Vc + 2048;            // [8][16][128]
    float* Zs      = partial + 16384;      // [16][128]
    float* sden    = Zs + 2048;            // [16]

    int blk = blockIdx.x;
    int b = blk >> 6, c = blk & 63;
    int tid = threadIdx.x, wid = tid >> 5, lane = tid & 31;
    int rowbase = b*T_ + c*CH;

    // state prefix loads first (independent of smem staging; maximize early MLP)
    float4 st[16];
    size_t pbase = ((size_t)(b*NC + c)*D_ + wid)*D_ + lane*4;
    #pragma unroll
    for (int r = 0; r < 16; r++)
        st[r] = __ldcs((const float4*)&g_kvsum[pbase + (size_t)r*8*D_]);

    for (int i = tid; i < CH*32; i += 256) {
        int t = i >> 5, c4 = (i & 31) * 4;
        const float* p = g_P + (size_t)(rowbase + t)*512;
        *(float4*)&Kc[t*128 + c4] = __ldcs((const float4*)(p + c4));
        *(float4*)&Qc[t*128 + c4] = __ldcs((const float4*)(p + 128 + c4));
        *(float4*)&Vc[t*128 + c4] = __ldcs((const float4*)(p + 256 + c4));
    }
    __syncthreads();

    // ---- main loop: NO barriers; streaming stores for write-once S ----
    for (int t = 0; t < CH; t++) {
        float4 v = *(const float4*)&Vc[t*128 + lane*4];
        float4 pn = make_float4(0.f,0.f,0.f,0.f);
        float* sbase = Sout + ((size_t)(rowbase + t)*D_ + wid)*D_ + lane*4;
        #pragma unroll
        for (int r = 0; r < 16; r++) {
            float k = Kc[t*128 + wid + 8*r];
            st[r].x += k*v.x; st[r].y += k*v.y; st[r].z += k*v.z; st[r].w += k*v.w;
            __stcs((float4*)(sbase + (size_t)r*8*D_), st[r]);
            float q = Qc[t*128 + wid + 8*r];
            pn.x += q*st[r].x; pn.y += q*st[r].y; pn.z += q*st[r].z; pn.w += q*st[r].w;
        }
        *(float4*)&partial[wid*2048 + t*128 + lane*4] = pn;
    }

    // ---- phase A: Z prefix within chunk ----
    if (tid < 128) {
        float zr = g_zsum[(size_t)(b*NC + c)*D_ + tid];
        #pragma unroll
        for (int t = 0; t < CH; t++) {
            zr += Kc[t*128 + tid];
            Zs[t*128 + tid] = zr;
            __stcs(&Zout[(size_t)(rowbase + t)*D_ + tid], zr);
        }
    }
    __syncthreads();

    // ---- phase B: den[t] = Q[t] . Z[t] ----
    #pragma unroll
    for (int s = 0; s < 2; s++) {
        int t = wid*2 + s;
        float dp = 0.f;
        #pragma unroll
        for (int jj = 0; jj < 4; jj++) {
            int j = lane + jj*32;
            dp += Qc[t*128 + j] * Zs[t*128 + j];
        }
        #pragma unroll
        for (int o = 16; o; o >>= 1) dp += __shfl_xor_sync(0xffffffffu, dp, o);
        if (lane == 0) sden[t] = dp;
    }
    __syncthreads();

    // ---- phase C: attn -> As (reuse Vc) ----
    float* As = Vc;
    #pragma unroll
    for (int k = 0; k < 8; k++) {
        int idx = tid + k*256;
        int t = idx >> 7, j = idx & 127;
        float num = 0.f;
        #pragma unroll
        for (int w = 0; w < 8; w++) num += partial[w*2048 + t*128 + j];
        As[t*128 + j] = num / (sden[t] + 1e-5f);
    }
    __syncthreads();

    // ---- phase D: MLP on 16 rows ----
    float* sW = partial;     // 128*WPAD = 16896 <= 18432 floats
    float* sH = Kc;          // 2048 <= 4096 floats

    int e  = tid & 127;
    int rr = (tid >> 7) * 8;

    #pragma unroll
    for (int rep = 0; rep < 16; rep++) {
        int i = rep*256 + tid;
        int ee = i >> 5, d4 = (i & 31) * 4;
        *(float4*)&sW[ee*WPAD + d4] = *(const float4*)(W1 + (size_t)ee*128 + d4);
    }
    __syncthreads();

    float acc[8];
    #pragma unroll
    for (int i = 0; i < 8; i++) acc[i] = 0.f;
    for (int d4 = 0; d4 < 128; d4 += 4) {
        float4 w = *(const float4*)&sW[e*WPAD + d4];
        #pragma unroll
        for (int i = 0; i < 8; i++) {
            float4 a = *(const float4*)&As[(rr + i)*128 + d4];
            acc[i] += a.x*w.x + a.y*w.y + a.z*w.z + a.w*w.w;
        }
    }
    float bb1 = __ldg(&b1[e]);
    #pragma unroll
    for (int i = 0; i < 8; i++)
        sH[(rr + i)*128 + e] = fmaxf(acc[i] + bb1, 0.f);
    __syncthreads();

    #pragma unroll
    for (int rep = 0; rep < 16; rep++) {
        int i = rep*256 + tid;
        int ee = i >> 5, d4 = (i & 31) * 4;
        *(float4*)&sW[ee*WPAD + d4] = *(const float4*)(W2 + (size_t)ee*128 + d4);
    }
    __syncthreads();

    #pragma unroll
    for (int i = 0; i < 8; i++) acc[i] = 0.f;
    for (int d4 = 0; d4 < 128; d4 += 4) {
        float4 w = *(const float4*)&sW[e*WPAD + d4];
        #pragma unroll
        for (int i = 0; i < 8; i++) {
            float4 a = *(const float4*)&sH[(rr + i)*128 + d4];
            acc[i] += a.x*w.x + a.y*w.y + a.z*w.z + a.w*w.w;
        }
    }
    float bb2 = __ldg(&b2[e]);
    float bse = __ldg(&bs[e]);
    #pragma unroll
    for (int i = 0; i < 8; i++) {
        size_t row = (size_t)(rowbase + rr + i);
        float sp = g_P[row*512 + 384 + e];
        __stcs(&out[row*128 + e], fmaxf(acc[i] + bb2, 0.f) + sp + bse);
    }
}

// ---------------- launcher ----------------
extern "C" void kernel_launch(void* const* d_in, const int* in_sizes, int n_in,
                              void* d_out, int out_size) {
    const float* x    = (const float*)d_in[0];
    const float* S0   = (const float*)d_in[1];
    const float* Z0   = (const float*)d_in[2];
    const float* ln_g = (const float*)d_in[3];
    const float* ln_b = (const float*)d_in[4];
    const float* Wk   = (const float*)d_in[5];
    const float* Wq   = (const float*)d_in[6];
    const float* Wv   = (const float*)d_in[7];
    const float* W1   = (const float*)d_in[8];
    const float* b1   = (const float*)d_in[9];
    const float* W2   = (const float*)d_in[10];
    const float* b2   = (const float*)d_in[11];
    const float* Ws   = (const float*)d_in[12];
    const float* bs   = (const float*)d_in[13];

    float* out  = (float*)d_out;
    float* Sout = out  + (size_t)BT*D_;
    float* Zout = Sout + (size_t)BT*D_*D_;

    ln_kernel<<<BT, 256>>>(x, ln_g, ln_b, Wk, Wq, Wv, Ws);
    cudaFuncSetAttribute(proj_gemm_bf16, cudaFuncAttributeMaxDynamicSharedMemorySize, PJ_SMEM);
    proj_gemm_bf16<<<dim3(BT/128, 4), 256, PJ_SMEM>>>();
    chunksum_kernel<<<B_*NC*2, 256>>>();
    prefix_kernel<<<258, 256>>>(S0, Z0);
    cudaFuncSetAttribute(scan_kernel, cudaFuncAttributeMaxDynamicSharedMemorySize, SC_SMEM);
    scan_kernel<<<B_*NC, 256, SC_SMEM>>>(W1, b1, W2, b2, bs, out, Sout, Zout);
}